// round 7
// baseline (speedup 1.0000x reference)
#include <cuda_runtime.h>
#include <math.h>

#define Nn 128
#define Hh 128
#define Ww 128
typedef unsigned long long ull;

// ---------------- device scratch (allocation-free) ----------------
__device__ __align__(16) float2 g_h2[Nn * Hh * Ww];   // conv1 out, channel-interleaved
__device__ __align__(16) float  g_actT[8192 * Nn];    // pooled activation, [k][n]
__device__ __align__(16) float  g_a1T[2048 * Nn];     // fc1 out, [o][n]
__device__ __align__(16) float  g_a2T[1024 * Nn];     // fc2 out, [o][n]

// ---------------- f32x2 helpers ----------------
__device__ __forceinline__ ull pack2(float lo, float hi) {
    ull r; asm("mov.b64 %0, {%1, %2};" : "=l"(r) : "f"(lo), "f"(hi)); return r;
}
__device__ __forceinline__ ull pack2dup(float v) {
    ull r; asm("mov.b64 %0, {%1, %1};" : "=l"(r) : "f"(v)); return r;
}
__device__ __forceinline__ void unpack2(ull v, float& a, float& b) {
    asm("mov.b64 {%0, %1}, %2;" : "=f"(a), "=f"(b) : "l"(v));
}
__device__ __forceinline__ ull fma2(ull a, ull b, ull c) {
    ull d; asm("fma.rn.f32x2 %0, %1, %2, %3;" : "=l"(d) : "l"(a), "l"(b), "l"(c)); return d;
}
__device__ __forceinline__ ull mul2(ull a, ull b) {
    ull d; asm("mul.rn.f32x2 %0, %1, %2;" : "=l"(d) : "l"(a), "l"(b)); return d;
}

// ---------------- cp.async helpers ----------------
__device__ __forceinline__ void cpa16(void* smem, const void* gmem) {
    unsigned s = (unsigned)__cvta_generic_to_shared(smem);
    asm volatile("cp.async.cg.shared.global [%0], [%1], 16;" :: "r"(s), "l"(gmem));
}
__device__ __forceinline__ void cpa_commit() { asm volatile("cp.async.commit_group;"); }
__device__ __forceinline__ void cpa_wait1()  { asm volatile("cp.async.wait_group 1;"); }
__device__ __forceinline__ void cpa_wait0()  { asm volatile("cp.async.wait_group 0;"); }

// ---------------- tf32 helpers ----------------
__device__ __forceinline__ unsigned cvt_tf32(float x) {
    unsigned r; asm("cvt.rna.tf32.f32 %0, %1;" : "=r"(r) : "f"(x)); return r;
}
__device__ __forceinline__ void split_tf32(float x, unsigned& h, unsigned& l) {
    h = cvt_tf32(x);
    l = cvt_tf32(x - __uint_as_float(h));
}
__device__ __forceinline__ void mma_tf32(float c[4],
    unsigned a0, unsigned a1, unsigned a2, unsigned a3,
    unsigned b0, unsigned b1)
{
    asm volatile(
        "mma.sync.aligned.m16n8k8.row.col.f32.tf32.tf32.f32 "
        "{%0,%1,%2,%3}, {%4,%5,%6,%7}, {%8,%9}, {%0,%1,%2,%3};\n"
        : "+f"(c[0]), "+f"(c[1]), "+f"(c[2]), "+f"(c[3])
        : "r"(a0), "r"(a1), "r"(a2), "r"(a3), "r"(b0), "r"(b1));
}

// ---------------- kernel 1: conv3x3 (9ch -> 2ch), pad 1, f32x2 over out-channels ----------------
__global__ __launch_bounds__(128) void conv1_kernel(
    const float* __restrict__ x, const float* __restrict__ mask,
    const float* __restrict__ w1, const float* __restrict__ b1)
{
    __shared__ ull ws2[81];
    int tid = threadIdx.x;
    if (tid < 81) ws2[tid] = pack2(w1[tid], w1[81 + tid]);
    __syncthreads();

    int j = tid, i = blockIdx.x, n = blockIdx.y;
    ull acc = pack2(b1[0], b1[1]);

    #pragma unroll
    for (int c = 0; c < 9; ++c) {
        const float* src = (c < 8) ? (x + (size_t)(n * 8 + c) * Hh * Ww)
                                   : (mask + (size_t)n * Hh * Ww);
        #pragma unroll
        for (int ky = 0; ky < 3; ++ky) {
            int yy = i + ky - 1;
            if (yy < 0 || yy >= Hh) continue;
            #pragma unroll
            for (int kx = 0; kx < 3; ++kx) {
                int xx = j + kx - 1;
                if (xx < 0 || xx >= Ww) continue;
                acc = fma2(pack2dup(src[yy * Ww + xx]), ws2[c * 9 + ky * 3 + kx], acc);
            }
        }
    }
    float a0, a1; unpack2(acc, a0, a1);
    g_h2[((size_t)n * Hh + i) * Ww + j] = make_float2(a0, a1);
}

// ---- kernel 2: fused dilated conv_off + sigmoid + DCN + 1x1 conv + relu + 2x2 maxpool ----
__global__ __launch_bounds__(128) void dcn_kernel(
    const float* __restrict__ w_off,
    const float* __restrict__ w_dcn, const float* __restrict__ b_dcn,
    const float* __restrict__ w2, const float* __restrict__ b2)
{
    __shared__ ull wof2[9 * 27];
    __shared__ ull wdA[9], wdB[9];
    __shared__ float bds[2], w2s[4], b2s[2];
    int tid = threadIdx.x;
    for (int t = tid; t < 243; t += 128) {
        int tap = t / 27, m = t % 27;
        wof2[t] = pack2(w_off[m * 18 + tap], w_off[m * 18 + 9 + tap]);
    }
    if (tid < 9) {
        wdA[tid] = pack2(w_dcn[tid],      w_dcn[9 + tid]);
        wdB[tid] = pack2(w_dcn[18 + tid], w_dcn[27 + tid]);
    }
    if (tid < 4) w2s[tid] = w2[tid];
    if (tid < 2) { bds[tid] = b_dcn[tid]; b2s[tid] = b2[tid]; }
    __syncthreads();

    int n  = blockIdx.y;
    int pi = blockIdx.x * 2 + (tid >> 6);
    int pj = tid & 63;

    const float2* hp = g_h2 + (size_t)n * Hh * Ww;
    const ull* hpu = (const ull*)hp;

    float mx0 = -INFINITY, mx1 = -INFINITY;

    #pragma unroll
    for (int di = 0; di < 2; ++di)
    #pragma unroll
    for (int dj = 0; dj < 2; ++dj) {
        int i = pi * 2 + di, j = pj * 2 + dj;

        ull om2[27];
        #pragma unroll
        for (int m = 0; m < 27; ++m) om2[m] = 0ULL;
        #pragma unroll
        for (int ky = 0; ky < 3; ++ky) {
            int yy = i + (ky - 1) * 3;
            if (yy < 0 || yy >= Hh) continue;
            #pragma unroll
            for (int kx = 0; kx < 3; ++kx) {
                int xx = j + (kx - 1) * 3;
                if (xx < 0 || xx >= Ww) continue;
                ull v2 = hpu[yy * Ww + xx];
                const ull* wp = &wof2[(ky * 3 + kx) * 27];
                #pragma unroll
                for (int m = 0; m < 27; ++m) om2[m] = fma2(v2, wp[m], om2[m]);
            }
        }
        float om[27];
        #pragma unroll
        for (int m = 0; m < 27; ++m) { float a, b; unpack2(om2[m], a, b); om[m] = a + b; }

        ull outA = 0ULL, outB = 0ULL;
        #pragma unroll
        for (int k = 0; k < 9; ++k) {
            float dyv = om[2 * k];
            float dxv = om[2 * k + 1];
            float mmv = 1.f / (1.f + __expf(-om[18 + k]));
            float py = dyv + (float)((k / 3 - 1) * 3 + i);
            float px = dxv + (float)((k % 3 - 1) * 3 + j);
            float y0f = floorf(py), x0f = floorf(px);
            int y0 = (int)y0f, x0 = (int)x0f;
            float ly = py - y0f, lx = px - x0f;
            float w00 = (1.f - ly) * (1.f - lx);
            float w01 = (1.f - ly) * lx;
            float w10 = ly * (1.f - lx);
            float w11 = ly * lx;
            ull s2 = 0ULL;
            bool xv0 = (x0 >= 0) && (x0 < Ww);
            bool xv1 = (x0 + 1 >= 0) && (x0 + 1 < Ww);
            if (y0 >= 0 && y0 < Hh) {
                const ull* row = hpu + y0 * Ww;
                if (xv0) s2 = fma2(row[x0],     pack2dup(w00), s2);
                if (xv1) s2 = fma2(row[x0 + 1], pack2dup(w01), s2);
            }
            if (y0 + 1 >= 0 && y0 + 1 < Hh) {
                const ull* row = hpu + (y0 + 1) * Ww;
                if (xv0) s2 = fma2(row[x0],     pack2dup(w10), s2);
                if (xv1) s2 = fma2(row[x0 + 1], pack2dup(w11), s2);
            }
            s2 = mul2(s2, pack2dup(mmv));
            outA = fma2(s2, wdA[k], outA);
            outB = fma2(s2, wdB[k], outB);
        }
        float a0, a1, c0, c1;
        unpack2(outA, a0, a1); unpack2(outB, c0, c1);
        float out0 = bds[0] + a0 + a1;
        float out1 = bds[1] + c0 + c1;

        float r0 = fmaxf(out0 * w2s[0] + out1 * w2s[1] + b2s[0], 0.f);
        float r1 = fmaxf(out0 * w2s[2] + out1 * w2s[3] + b2s[1], 0.f);
        mx0 = fmaxf(mx0, r0);
        mx1 = fmaxf(mx1, r1);
    }

    int pk = pi * 64 + pj;
    g_actT[(size_t)(0    + pk) * Nn + n] = mx0;
    g_actT[(size_t)(4096 + pk) * Nn + n] = mx1;
}

// ---------------- FC GEMM via tf32 MMA (3x split for fp32 accuracy) ----------------
// OutT[o][n] = act(W[o][:]·A[:][n] + b[o]); A is [K][128], O_TILE=16 per block.
// Block: 256 threads = 8 warps; warp w covers N-tiles {2w, 2w+1} (n = 16w..16w+15).
// mma m16n8k8: M=o, N=n, K=k. g = lane>>2, t = lane&3.
#define AS_STRIDE 132
#define WS_STRIDE 36

template<int K, bool RELU>
__device__ __forceinline__ void fc_mma_body(
    const float* __restrict__ W, const float* __restrict__ bias,
    const float* __restrict__ A, float* __restrict__ OutT)
{
    __shared__ __align__(16) float As[2][32 * AS_STRIDE];
    __shared__ __align__(16) float Ws[2][16 * WS_STRIDE];

    int tid  = threadIdx.x;
    int warp = tid >> 5;
    int lane = tid & 31;
    int g = lane >> 2;       // 0..7 : o-row within tile / n-col within tile
    int t = lane & 3;        // 0..3 : k
    int o0 = blockIdx.x * 16;

    float acc[2][4];
    #pragma unroll
    for (int nt = 0; nt < 2; ++nt)
        #pragma unroll
        for (int r = 0; r < 4; ++r) acc[nt][r] = 0.f;

    const int NCH = K / 32;

    auto load_chunk = [&](int c, int buf) {
        const float* Ag = A + (size_t)c * 32 * 128;
        #pragma unroll
        for (int r = 0; r < 4; ++r) {
            int q = tid + r * 256;           // 1024 segments of 16B
            int kk = q >> 5, sg = q & 31;
            cpa16(&As[buf][kk * AS_STRIDE + sg * 4], Ag + kk * 128 + sg * 4);
        }
        if (tid < 128) {
            int oo = tid >> 3, sg = tid & 7;
            cpa16(&Ws[buf][oo * WS_STRIDE + sg * 4],
                  W + (size_t)(o0 + oo) * K + c * 32 + sg * 4);
        }
    };

    load_chunk(0, 0);
    cpa_commit();

    for (int c = 0; c < NCH; ++c) {
        int buf = c & 1;
        if (c + 1 < NCH) {
            load_chunk(c + 1, buf ^ 1);
            cpa_commit();
            cpa_wait1();
        } else {
            cpa_wait0();
        }
        __syncthreads();

        const float* Ab = As[buf];
        const float* Wb = Ws[buf];

        #pragma unroll
        for (int s = 0; s < 4; ++s) {        // 4 k-steps of 8 within the 32-chunk
            int k0 = s * 8;
            // A fragment (W matrix tile, 16x8)
            float a0f = Wb[g * WS_STRIDE + k0 + t];
            float a1f = Wb[(g + 8) * WS_STRIDE + k0 + t];
            float a2f = Wb[g * WS_STRIDE + k0 + 4 + t];
            float a3f = Wb[(g + 8) * WS_STRIDE + k0 + 4 + t];
            unsigned ah0, al0, ah1, al1, ah2, al2, ah3, al3;
            split_tf32(a0f, ah0, al0);
            split_tf32(a1f, ah1, al1);
            split_tf32(a2f, ah2, al2);
            split_tf32(a3f, ah3, al3);

            #pragma unroll
            for (int nt = 0; nt < 2; ++nt) {
                int n0 = warp * 16 + nt * 8;
                float b0f = Ab[(k0 + t) * AS_STRIDE + n0 + g];
                float b1f = Ab[(k0 + 4 + t) * AS_STRIDE + n0 + g];
                unsigned bh0, bl0, bh1, bl1;
                split_tf32(b0f, bh0, bl0);
                split_tf32(b1f, bh1, bl1);

                mma_tf32(acc[nt], ah0, ah1, ah2, ah3, bh0, bh1);
                mma_tf32(acc[nt], ah0, ah1, ah2, ah3, bl0, bl1);
                mma_tf32(acc[nt], al0, al1, al2, al3, bh0, bh1);
            }
        }
        __syncthreads();
    }

    // epilogue: d0,d1 -> (o0+g, n0+2t, +1); d2,d3 -> (o0+8+g, ...)
    int o_lo = o0 + g, o_hi = o0 + 8 + g;
    float b_lo = bias[o_lo], b_hi = bias[o_hi];
    #pragma unroll
    for (int nt = 0; nt < 2; ++nt) {
        int n = warp * 16 + nt * 8 + 2 * t;
        float v0 = acc[nt][0] + b_lo;
        float v1 = acc[nt][1] + b_lo;
        float v2 = acc[nt][2] + b_hi;
        float v3 = acc[nt][3] + b_hi;
        if (RELU) {
            v0 = fmaxf(v0, 0.f); v1 = fmaxf(v1, 0.f);
            v2 = fmaxf(v2, 0.f); v3 = fmaxf(v3, 0.f);
        }
        *(float2*)(OutT + (size_t)o_lo * 128 + n) = make_float2(v0, v1);
        *(float2*)(OutT + (size_t)o_hi * 128 + n) = make_float2(v2, v3);
    }
}

__global__ __launch_bounds__(256) void fc1_kernel(const float* __restrict__ W,
                                                  const float* __restrict__ b)
{
    fc_mma_body<8192, true>(W, b, g_actT, g_a1T);
}

__global__ __launch_bounds__(256) void fc2_kernel(const float* __restrict__ W,
                                                  const float* __restrict__ b)
{
    fc_mma_body<2048, true>(W, b, g_a1T, g_a2T);
}

// ---------------- FC3 + sigmoid: one block per n ----------------
__global__ __launch_bounds__(256) void fc3_kernel(const float* __restrict__ io_w,
                                                  const float* __restrict__ io_b,
                                                  float* __restrict__ out)
{
    __shared__ float red[256];
    int n = blockIdx.x, tid = threadIdx.x;
    float acc = 0.f;
    #pragma unroll 4
    for (int k = tid; k < 1024; k += 256)
        acc += g_a2T[(size_t)k * 128 + n] * io_w[k];
    red[tid] = acc;
    __syncthreads();
    #pragma unroll
    for (int s = 128; s > 0; s >>= 1) {
        if (tid < s) red[tid] += red[tid + s];
        __syncthreads();
    }
    if (tid == 0) out[n] = 1.f / (1.f + __expf(-(red[0] + io_b[0])));
}

// ---------------- launch ----------------
extern "C" void kernel_launch(void* const* d_in, const int* in_sizes, int n_in,
                              void* d_out, int out_size)
{
    const float* mask  = (const float*)d_in[0];
    const float* x     = (const float*)d_in[1];
    const float* w1    = (const float*)d_in[2];
    const float* b1    = (const float*)d_in[3];
    const float* w_off = (const float*)d_in[4];
    const float* w_dcn = (const float*)d_in[5];
    const float* b_dcn = (const float*)d_in[6];
    const float* w2    = (const float*)d_in[7];
    const float* b2    = (const float*)d_in[8];
    const float* fc1_w = (const float*)d_in[9];
    const float* fc1_b = (const float*)d_in[10];
    const float* fc2_w = (const float*)d_in[11];
    const float* fc2_b = (const float*)d_in[12];
    const float* io_w  = (const float*)d_in[13];
    const float* io_b  = (const float*)d_in[14];
    float* out = (float*)d_out;

    dim3 g1(Hh, Nn);
    conv1_kernel<<<g1, 128>>>(x, mask, w1, b1);

    dim3 g2(32, Nn);
    dcn_kernel<<<g2, 128>>>(w_off, w_dcn, b_dcn, w2, b2);

    fc1_kernel<<<2048 / 16, 256>>>(fc1_w, fc1_b);
    fc2_kernel<<<1024 / 16, 256>>>(fc2_w, fc2_b);
    fc3_kernel<<<128, 256>>>(io_w, io_b, out);
}

// round 8
// speedup vs baseline: 1.3904x; 1.3904x over previous
#include <cuda_runtime.h>
#include <cuda_bf16.h>
#include <math.h>

#define Nn 128
#define Hh 128
#define Ww 128
typedef unsigned long long ull;
typedef unsigned int u32;

// ---------------- device scratch (allocation-free) ----------------
__device__ __align__(16) float2 g_h2[Nn * Hh * Ww];     // conv1 out, channel-interleaved
__device__ __align__(16) u32   g_b1H[128 * 4096];       // fc1 input, bf16 hi, [n][kp] (k-pairs)
__device__ __align__(16) u32   g_b1L[128 * 4096];       // fc1 input, bf16 lo
__device__ __align__(16) float g_part1[4 * 2048 * 128]; // fc1 partials [ks][o][n]
__device__ __align__(16) u32   g_b2H[128 * 1024];       // fc2 input hi, [n][kp]
__device__ __align__(16) u32   g_b2L[128 * 1024];       // fc2 input lo
__device__ __align__(16) float g_part2[8 * 1024 * 128]; // fc2 partials [ks][o][n]
__device__ __align__(16) float g_a2N[128 * 1024];       // fc2 out, [n][o]

// ---------------- f32x2 helpers ----------------
__device__ __forceinline__ ull pack2(float lo, float hi) {
    ull r; asm("mov.b64 %0, {%1, %2};" : "=l"(r) : "f"(lo), "f"(hi)); return r;
}
__device__ __forceinline__ ull pack2dup(float v) {
    ull r; asm("mov.b64 %0, {%1, %1};" : "=l"(r) : "f"(v)); return r;
}
__device__ __forceinline__ void unpack2(ull v, float& a, float& b) {
    asm("mov.b64 {%0, %1}, %2;" : "=f"(a), "=f"(b) : "l"(v));
}
__device__ __forceinline__ ull fma2(ull a, ull b, ull c) {
    ull d; asm("fma.rn.f32x2 %0, %1, %2, %3;" : "=l"(d) : "l"(a), "l"(b), "l"(c)); return d;
}
__device__ __forceinline__ ull mul2(ull a, ull b) {
    ull d; asm("mul.rn.f32x2 %0, %1, %2;" : "=l"(d) : "l"(a), "l"(b)); return d;
}

// ---------------- bf16 split helpers ----------------
__device__ __forceinline__ u32 pack_bf16(float a, float b) {
    __nv_bfloat162 h; h.x = __float2bfloat16(a); h.y = __float2bfloat16(b);
    return *reinterpret_cast<u32*>(&h);
}
__device__ __forceinline__ float bf16_res(float v) {
    return v - __bfloat162float(__float2bfloat16(v));
}
__device__ __forceinline__ void mma_bf16(float c[4],
    u32 a0, u32 a1, u32 a2, u32 a3, u32 b0, u32 b1)
{
    asm volatile(
        "mma.sync.aligned.m16n8k16.row.col.f32.bf16.bf16.f32 "
        "{%0,%1,%2,%3}, {%4,%5,%6,%7}, {%8,%9}, {%0,%1,%2,%3};\n"
        : "+f"(c[0]), "+f"(c[1]), "+f"(c[2]), "+f"(c[3])
        : "r"(a0), "r"(a1), "r"(a2), "r"(a3), "r"(b0), "r"(b1));
}

// ---------------- kernel 1: conv3x3 (9ch -> 2ch), pad 1 ----------------
__global__ __launch_bounds__(128) void conv1_kernel(
    const float* __restrict__ x, const float* __restrict__ mask,
    const float* __restrict__ w1, const float* __restrict__ b1)
{
    __shared__ ull ws2[81];
    int tid = threadIdx.x;
    if (tid < 81) ws2[tid] = pack2(w1[tid], w1[81 + tid]);
    __syncthreads();

    int j = tid, i = blockIdx.x, n = blockIdx.y;
    ull acc = pack2(b1[0], b1[1]);

    #pragma unroll
    for (int c = 0; c < 9; ++c) {
        const float* src = (c < 8) ? (x + (size_t)(n * 8 + c) * Hh * Ww)
                                   : (mask + (size_t)n * Hh * Ww);
        #pragma unroll
        for (int ky = 0; ky < 3; ++ky) {
            int yy = i + ky - 1;
            if (yy < 0 || yy >= Hh) continue;
            #pragma unroll
            for (int kx = 0; kx < 3; ++kx) {
                int xx = j + kx - 1;
                if (xx < 0 || xx >= Ww) continue;
                acc = fma2(pack2dup(src[yy * Ww + xx]), ws2[c * 9 + ky * 3 + kx], acc);
            }
        }
    }
    float a0, a1; unpack2(acc, a0, a1);
    g_h2[((size_t)n * Hh + i) * Ww + j] = make_float2(a0, a1);
}

// ---- kernel 2: fused dilated conv_off + sigmoid + DCN + 1x1 conv + relu + 2x2 maxpool ----
// epilogue: pack adjacent-pixel pairs as bf16 hi/lo for the fc1 GEMM's B operand
__global__ __launch_bounds__(128) void dcn_kernel(
    const float* __restrict__ w_off,
    const float* __restrict__ w_dcn, const float* __restrict__ b_dcn,
    const float* __restrict__ w2, const float* __restrict__ b2)
{
    __shared__ ull wof2[9 * 27];
    __shared__ ull wdA[9], wdB[9];
    __shared__ float bds[2], w2s[4], b2s[2];
    int tid = threadIdx.x;
    for (int t = tid; t < 243; t += 128) {
        int tap = t / 27, m = t % 27;
        wof2[t] = pack2(w_off[m * 18 + tap], w_off[m * 18 + 9 + tap]);
    }
    if (tid < 9) {
        wdA[tid] = pack2(w_dcn[tid],      w_dcn[9 + tid]);
        wdB[tid] = pack2(w_dcn[18 + tid], w_dcn[27 + tid]);
    }
    if (tid < 4) w2s[tid] = w2[tid];
    if (tid < 2) { bds[tid] = b_dcn[tid]; b2s[tid] = b2[tid]; }
    __syncthreads();

    int n  = blockIdx.y;
    int pi = blockIdx.x * 2 + (tid >> 6);
    int pj = tid & 63;

    const float2* hp = g_h2 + (size_t)n * Hh * Ww;
    const ull* hpu = (const ull*)hp;

    float mx0 = -INFINITY, mx1 = -INFINITY;

    #pragma unroll
    for (int di = 0; di < 2; ++di)
    #pragma unroll
    for (int dj = 0; dj < 2; ++dj) {
        int i = pi * 2 + di, j = pj * 2 + dj;

        ull om2[27];
        #pragma unroll
        for (int m = 0; m < 27; ++m) om2[m] = 0ULL;
        #pragma unroll
        for (int ky = 0; ky < 3; ++ky) {
            int yy = i + (ky - 1) * 3;
            if (yy < 0 || yy >= Hh) continue;
            #pragma unroll
            for (int kx = 0; kx < 3; ++kx) {
                int xx = j + (kx - 1) * 3;
                if (xx < 0 || xx >= Ww) continue;
                ull v2 = hpu[yy * Ww + xx];
                const ull* wp = &wof2[(ky * 3 + kx) * 27];
                #pragma unroll
                for (int m = 0; m < 27; ++m) om2[m] = fma2(v2, wp[m], om2[m]);
            }
        }
        float om[27];
        #pragma unroll
        for (int m = 0; m < 27; ++m) { float a, b; unpack2(om2[m], a, b); om[m] = a + b; }

        ull outA = 0ULL, outB = 0ULL;
        #pragma unroll
        for (int k = 0; k < 9; ++k) {
            float dyv = om[2 * k];
            float dxv = om[2 * k + 1];
            float mmv = 1.f / (1.f + __expf(-om[18 + k]));
            float py = dyv + (float)((k / 3 - 1) * 3 + i);
            float px = dxv + (float)((k % 3 - 1) * 3 + j);
            float y0f = floorf(py), x0f = floorf(px);
            int y0 = (int)y0f, x0 = (int)x0f;
            float ly = py - y0f, lx = px - x0f;
            float w00 = (1.f - ly) * (1.f - lx);
            float w01 = (1.f - ly) * lx;
            float w10 = ly * (1.f - lx);
            float w11 = ly * lx;
            ull s2 = 0ULL;
            bool xv0 = (x0 >= 0) && (x0 < Ww);
            bool xv1 = (x0 + 1 >= 0) && (x0 + 1 < Ww);
            if (y0 >= 0 && y0 < Hh) {
                const ull* row = hpu + y0 * Ww;
                if (xv0) s2 = fma2(row[x0],     pack2dup(w00), s2);
                if (xv1) s2 = fma2(row[x0 + 1], pack2dup(w01), s2);
            }
            if (y0 + 1 >= 0 && y0 + 1 < Hh) {
                const ull* row = hpu + (y0 + 1) * Ww;
                if (xv0) s2 = fma2(row[x0],     pack2dup(w10), s2);
                if (xv1) s2 = fma2(row[x0 + 1], pack2dup(w11), s2);
            }
            s2 = mul2(s2, pack2dup(mmv));
            outA = fma2(s2, wdA[k], outA);
            outB = fma2(s2, wdB[k], outB);
        }
        float a0, a1, c0, c1;
        unpack2(outA, a0, a1); unpack2(outB, c0, c1);
        float out0 = bds[0] + a0 + a1;
        float out1 = bds[1] + c0 + c1;

        float r0 = fmaxf(out0 * w2s[0] + out1 * w2s[1] + b2s[0], 0.f);
        float r1 = fmaxf(out0 * w2s[2] + out1 * w2s[3] + b2s[1], 0.f);
        mx0 = fmaxf(mx0, r0);
        mx1 = fmaxf(mx1, r1);
    }

    // pack (even,odd) pixel pairs along k: partner lives in adjacent lane
    float p0 = __shfl_down_sync(0xffffffffu, mx0, 1);
    float p1 = __shfl_down_sync(0xffffffffu, mx1, 1);
    if (!(pj & 1)) {
        int kp = (pi * 64 + pj) >> 1;          // 0..2047 within channel
        size_t base = (size_t)n * 4096;
        g_b1H[base + kp]        = pack_bf16(mx0, p0);
        g_b1L[base + kp]        = pack_bf16(bf16_res(mx0), bf16_res(p0));
        g_b1H[base + 2048 + kp] = pack_bf16(mx1, p1);
        g_b1L[base + 2048 + kp] = pack_bf16(bf16_res(mx1), bf16_res(p1));
    }
}

// ---------------- bf16-split FC GEMM ----------------
// part[ks][o][n] += W[o][kslice]·B[kslice][n] with 3-term bf16 split.
// Block: 256 thr = 8 warps (wm = warp>>1 over o, wn = warp&1 over n-halves).
// OT=64 o per block, N=128, chunk = 32 k (16 kp). Conflict-free stride-20 smem.
template<int KFULL, int BSTR, int KSLICE, int MTOT, int SEL>
__global__ __launch_bounds__(256, 1) void fc_mma_bf16(const float* __restrict__ W)
{
    constexpr int NCH = KSLICE / 32;
    __shared__ u32 WsH[64 * 20], WsL[64 * 20];
    __shared__ u32 BsH[128 * 20], BsL[128 * 20];

    const u32* __restrict__ BHg = (SEL == 0) ? g_b1H : g_b2H;
    const u32* __restrict__ BLg = (SEL == 0) ? g_b1L : g_b2L;
    float* __restrict__ part    = (SEL == 0) ? g_part1 : g_part2;

    int tid = threadIdx.x, warp = tid >> 5, lane = tid & 31;
    int g = lane >> 2, tq = lane & 3;
    int wm = warp >> 1, wn = warp & 1;
    int o0 = blockIdx.x * 64, ks = blockIdx.y;
    const float* Wb = W + (size_t)o0 * KFULL + (size_t)ks * KSLICE;
    int bko = ks * (KSLICE / 2);

    int wo = tid >> 2, wseg = tid & 3;        // W stage: o row, 8-float segment
    int bn = tid >> 1, bw = tid & 1;          // B stage: n row, hi/lo select
    const u32* Bsrc = bw ? BLg : BHg;
    u32* Bdst = bw ? BsL : BsH;

    float wreg[8];
    uint4 breg[4];

    float acc[8][4];
    #pragma unroll
    for (int i = 0; i < 8; ++i) { acc[i][0] = acc[i][1] = acc[i][2] = acc[i][3] = 0.f; }

    auto LDG = [&](int c) {
        const float4* wp = (const float4*)(Wb + (size_t)wo * KFULL + c * 32 + wseg * 8);
        float4 w0 = wp[0], w1 = wp[1];
        wreg[0] = w0.x; wreg[1] = w0.y; wreg[2] = w0.z; wreg[3] = w0.w;
        wreg[4] = w1.x; wreg[5] = w1.y; wreg[6] = w1.z; wreg[7] = w1.w;
        const uint4* bp = (const uint4*)(Bsrc + (size_t)bn * BSTR + bko + c * 16);
        breg[0] = bp[0]; breg[1] = bp[1]; breg[2] = bp[2]; breg[3] = bp[3];
    };
    auto STS = [&]() {
        u32 h[4], l[4];
        #pragma unroll
        for (int i = 0; i < 4; ++i) {
            h[i] = pack_bf16(wreg[2 * i], wreg[2 * i + 1]);
            l[i] = pack_bf16(bf16_res(wreg[2 * i]), bf16_res(wreg[2 * i + 1]));
        }
        *(uint4*)(WsH + wo * 20 + wseg * 4) = make_uint4(h[0], h[1], h[2], h[3]);
        *(uint4*)(WsL + wo * 20 + wseg * 4) = make_uint4(l[0], l[1], l[2], l[3]);
        uint4* bd = (uint4*)(Bdst + bn * 20);
        bd[0] = breg[0]; bd[1] = breg[1]; bd[2] = breg[2]; bd[3] = breg[3];
    };
    auto COMPUTE = [&]() {
        #pragma unroll
        for (int s = 0; s < 2; ++s) {
            int kp = s * 8 + tq;
            int ro = (16 * wm + g) * 20;
            u32 ah0 = WsH[ro + kp],       ah1 = WsH[ro + 160 + kp];
            u32 ah2 = WsH[ro + kp + 4],   ah3 = WsH[ro + 160 + kp + 4];
            u32 al0 = WsL[ro + kp],       al1 = WsL[ro + 160 + kp];
            u32 al2 = WsL[ro + kp + 4],   al3 = WsL[ro + 160 + kp + 4];
            #pragma unroll
            for (int nt = 0; nt < 8; ++nt) {
                int rn = (64 * wn + 8 * nt + g) * 20;
                u32 bh0 = BsH[rn + kp], bh1 = BsH[rn + kp + 4];
                u32 bl0 = BsL[rn + kp], bl1 = BsL[rn + kp + 4];
                mma_bf16(acc[nt], ah0, ah1, ah2, ah3, bh0, bh1);
                mma_bf16(acc[nt], ah0, ah1, ah2, ah3, bl0, bl1);
                mma_bf16(acc[nt], al0, al1, al2, al3, bh0, bh1);
            }
        }
    };

    LDG(0); STS();
    __syncthreads();
    if (NCH > 1) LDG(1);

    for (int c = 0; c < NCH; ++c) {
        COMPUTE();
        __syncthreads();
        if (c + 1 < NCH) STS();
        if (c + 2 < NCH) LDG(c + 2);
        __syncthreads();
    }

    int oL = o0 + 16 * wm + g;
    float* pbase = part + (size_t)ks * MTOT * 128;
    #pragma unroll
    for (int nt = 0; nt < 8; ++nt) {
        int n = 64 * wn + 8 * nt + 2 * tq;
        *(float2*)(pbase + (size_t)oL * 128 + n)       = make_float2(acc[nt][0], acc[nt][1]);
        *(float2*)(pbase + (size_t)(oL + 8) * 128 + n) = make_float2(acc[nt][2], acc[nt][3]);
    }
}

// ---------------- reduce 1: fc1 partials -> bias+relu -> bf16 hi/lo for fc2 ----------------
__global__ __launch_bounds__(256) void red1_kernel(const float* __restrict__ bias)
{
    int idx = blockIdx.x * 256 + threadIdx.x;   // 131072
    int n = idx & 127, kp = idx >> 7;           // kp 0..1023
    int o = 2 * kp;
    float v0 = bias[o], v1 = bias[o + 1];
    #pragma unroll
    for (int ks = 0; ks < 4; ++ks) {
        v0 += g_part1[((size_t)ks * 2048 + o) * 128 + n];
        v1 += g_part1[((size_t)ks * 2048 + o + 1) * 128 + n];
    }
    v0 = fmaxf(v0, 0.f); v1 = fmaxf(v1, 0.f);
    g_b2H[(size_t)n * 1024 + kp] = pack_bf16(v0, v1);
    g_b2L[(size_t)n * 1024 + kp] = pack_bf16(bf16_res(v0), bf16_res(v1));
}

// ---------------- reduce 2: fc2 partials -> bias+relu -> a2N [n][o] ----------------
__global__ __launch_bounds__(256) void red2_kernel(const float* __restrict__ bias)
{
    int idx = blockIdx.x * 256 + threadIdx.x;   // 131072
    int n = idx & 127, o = idx >> 7;
    float v = bias[o];
    #pragma unroll
    for (int ks = 0; ks < 8; ++ks)
        v += g_part2[((size_t)ks * 1024 + o) * 128 + n];
    g_a2N[(size_t)n * 1024 + o] = fmaxf(v, 0.f);
}

// ---------------- FC3 + sigmoid: one block per n ----------------
__global__ __launch_bounds__(256) void fc3_kernel(const float* __restrict__ io_w,
                                                  const float* __restrict__ io_b,
                                                  float* __restrict__ out)
{
    __shared__ float red[256];
    int n = blockIdx.x, tid = threadIdx.x;
    float acc = 0.f;
    #pragma unroll 4
    for (int k = tid; k < 1024; k += 256)
        acc += g_a2N[(size_t)n * 1024 + k] * io_w[k];
    red[tid] = acc;
    __syncthreads();
    #pragma unroll
    for (int s = 128; s > 0; s >>= 1) {
        if (tid < s) red[tid] += red[tid + s];
        __syncthreads();
    }
    if (tid == 0) out[n] = 1.f / (1.f + __expf(-(red[0] + io_b[0])));
}

// ---------------- launch ----------------
extern "C" void kernel_launch(void* const* d_in, const int* in_sizes, int n_in,
                              void* d_out, int out_size)
{
    const float* mask  = (const float*)d_in[0];
    const float* x     = (const float*)d_in[1];
    const float* w1    = (const float*)d_in[2];
    const float* b1    = (const float*)d_in[3];
    const float* w_off = (const float*)d_in[4];
    const float* w_dcn = (const float*)d_in[5];
    const float* b_dcn = (const float*)d_in[6];
    const float* w2    = (const float*)d_in[7];
    const float* b2    = (const float*)d_in[8];
    const float* fc1_w = (const float*)d_in[9];
    const float* fc1_b = (const float*)d_in[10];
    const float* fc2_w = (const float*)d_in[11];
    const float* fc2_b = (const float*)d_in[12];
    const float* io_w  = (const float*)d_in[13];
    const float* io_b  = (const float*)d_in[14];
    float* out = (float*)d_out;

    dim3 g1(Hh, Nn);
    conv1_kernel<<<g1, 128>>>(x, mask, w1, b1);

    dim3 g2(32, Nn);
    dcn_kernel<<<g2, 128>>>(w_off, w_dcn, b_dcn, w2, b2);

    // fc1: M=2048, K=8192, KS=4 -> 32x4 = 128 blocks
    fc_mma_bf16<8192, 4096, 2048, 2048, 0><<<dim3(32, 4), 256>>>(fc1_w);
    red1_kernel<<<512, 256>>>(fc1_b);

    // fc2: M=1024, K=2048, KS=8 -> 16x8 = 128 blocks
    fc_mma_bf16<2048, 1024, 256, 1024, 1><<<dim3(16, 8), 256>>>(fc2_w);
    red2_kernel<<<512, 256>>>(fc2_b);

    fc3_kernel<<<128, 256>>>(io_w, io_b, out);
}

// round 9
// speedup vs baseline: 1.4700x; 1.0572x over previous
#include <cuda_runtime.h>
#include <cuda_bf16.h>
#include <math.h>

#define Nn 128
#define Hh 128
#define Ww 128
typedef unsigned long long ull;
typedef unsigned int u32;

// ---------------- device scratch (allocation-free) ----------------
__device__ __align__(16) float2 g_h2[Nn * Hh * Ww];     // conv1 out, channel-interleaved
__device__ __align__(16) u32   g_b1H[128 * 4096];       // fc1 input, bf16 hi, [n][kp]
__device__ __align__(16) u32   g_b1L[128 * 4096];       // fc1 input, bf16 lo
__device__ __align__(16) float g_part1[4 * 2048 * 128]; // fc1 partials [ks][o][n]
__device__ __align__(16) u32   g_b2H[128 * 1024];       // fc2 input hi, [n][kp]
__device__ __align__(16) u32   g_b2L[128 * 1024];       // fc2 input lo
__device__ __align__(16) float g_part2[8 * 1024 * 128]; // fc2 partials [ks][o][n]
__device__ __align__(16) float g_a2N[128 * 1024];       // fc2 out, [n][o]
__device__ float g_dummy[32];

// ---------------- f32x2 helpers ----------------
__device__ __forceinline__ ull pack2(float lo, float hi) {
    ull r; asm("mov.b64 %0, {%1, %2};" : "=l"(r) : "f"(lo), "f"(hi)); return r;
}
__device__ __forceinline__ ull pack2dup(float v) {
    ull r; asm("mov.b64 %0, {%1, %1};" : "=l"(r) : "f"(v)); return r;
}
__device__ __forceinline__ void unpack2(ull v, float& a, float& b) {
    asm("mov.b64 {%0, %1}, %2;" : "=f"(a), "=f"(b) : "l"(v));
}
__device__ __forceinline__ ull fma2(ull a, ull b, ull c) {
    ull d; asm("fma.rn.f32x2 %0, %1, %2, %3;" : "=l"(d) : "l"(a), "l"(b), "l"(c)); return d;
}
__device__ __forceinline__ ull mul2(ull a, ull b) {
    ull d; asm("mul.rn.f32x2 %0, %1, %2;" : "=l"(d) : "l"(a), "l"(b)); return d;
}

// ---------------- bf16 split helpers ----------------
__device__ __forceinline__ u32 pack_bf16(float a, float b) {
    __nv_bfloat162 h; h.x = __float2bfloat16(a); h.y = __float2bfloat16(b);
    return *reinterpret_cast<u32*>(&h);
}
__device__ __forceinline__ float bf16_res(float v) {
    return v - __bfloat162float(__float2bfloat16(v));
}
__device__ __forceinline__ void mma_bf16(float c[4],
    u32 a0, u32 a1, u32 a2, u32 a3, u32 b0, u32 b1)
{
    asm volatile(
        "mma.sync.aligned.m16n8k16.row.col.f32.bf16.bf16.f32 "
        "{%0,%1,%2,%3}, {%4,%5,%6,%7}, {%8,%9}, {%0,%1,%2,%3};\n"
        : "+f"(c[0]), "+f"(c[1]), "+f"(c[2]), "+f"(c[3])
        : "r"(a0), "r"(a1), "r"(a2), "r"(a3), "r"(b0), "r"(b1));
}

// ---------------- dummy kernels (shift ncu capture slot onto dcn) ----------------
__global__ void warm_kernel(int v) {
    if (threadIdx.x < 32) g_dummy[threadIdx.x] = (float)v;
}

// ---------------- kernel 1: conv3x3 (9ch -> 2ch), pad 1, 4 px/thread ----------------
__global__ __launch_bounds__(128) void conv1_kernel(
    const float* __restrict__ x, const float* __restrict__ mask,
    const float* __restrict__ w1, const float* __restrict__ b1)
{
    __shared__ ull ws2[81];
    int tid = threadIdx.x;
    if (tid < 81) ws2[tid] = pack2(w1[tid], w1[81 + tid]);
    __syncthreads();

    int r = tid >> 5, q = tid & 31;
    int i = blockIdx.x * 4 + r;
    int j0 = q * 4;
    int n = blockIdx.y;

    ull acc[4];
    ull binit = pack2(b1[0], b1[1]);
    #pragma unroll
    for (int p = 0; p < 4; ++p) acc[p] = binit;

    #pragma unroll
    for (int c = 0; c < 9; ++c) {
        const float* src = (c < 8) ? (x + (size_t)(n * 8 + c) * Hh * Ww)
                                   : (mask + (size_t)n * Hh * Ww);
        #pragma unroll
        for (int ky = 0; ky < 3; ++ky) {
            int yy = i + ky - 1;
            if (yy < 0 || yy >= Hh) continue;
            const float* row = src + yy * Ww + j0;
            float win[6];
            win[0] = (j0 > 0) ? row[-1] : 0.f;
            float4 v = *(const float4*)row;
            win[1] = v.x; win[2] = v.y; win[3] = v.z; win[4] = v.w;
            win[5] = (j0 < 124) ? row[4] : 0.f;
            #pragma unroll
            for (int kx = 0; kx < 3; ++kx) {
                ull wk = ws2[c * 9 + ky * 3 + kx];
                #pragma unroll
                for (int p = 0; p < 4; ++p)
                    acc[p] = fma2(pack2dup(win[p + kx]), wk, acc[p]);
            }
        }
    }
    #pragma unroll
    for (int p = 0; p < 4; ++p) {
        float a0, a1; unpack2(acc[p], a0, a1);
        g_h2[((size_t)n * Hh + i) * Ww + j0 + p] = make_float2(a0, a1);
    }
}

// ---- kernel 2: fused dilated conv_off + sigmoid + DCN + 1x1 conv + relu + 2x2 maxpool ----
// 1 pixel per thread; block covers 2 rows x 128 cols; pool via shfl.
__global__ __launch_bounds__(256) void dcn_kernel(
    const float* __restrict__ w_off,
    const float* __restrict__ w_dcn, const float* __restrict__ b_dcn,
    const float* __restrict__ w2, const float* __restrict__ b2)
{
    __shared__ ull wof2[9 * 27];
    __shared__ ull wdA[9], wdB[9];
    __shared__ float bds[2], w2s[4], b2s[2];
    int tid = threadIdx.x;
    for (int t = tid; t < 243; t += 256) {
        int tap = t / 27, m = t % 27;
        wof2[t] = pack2(w_off[m * 18 + tap], w_off[m * 18 + 9 + tap]);
    }
    if (tid < 9) {
        wdA[tid] = pack2(w_dcn[tid],      w_dcn[9 + tid]);
        wdB[tid] = pack2(w_dcn[18 + tid], w_dcn[27 + tid]);
    }
    if (tid < 4) w2s[tid] = w2[tid];
    if (tid < 2) { bds[tid] = b_dcn[tid]; b2s[tid] = b2[tid]; }
    __syncthreads();

    int n  = blockIdx.y;
    int pi = blockIdx.x;              // pooled row 0..63
    int i  = pi * 2 + (tid & 1);      // image row
    int j  = tid >> 1;                // image col 0..127

    const ull* hpu = (const ull*)(g_h2 + (size_t)n * Hh * Ww);

    // conv_off: dilation 3, pad 3
    ull om2[27];
    #pragma unroll
    for (int m = 0; m < 27; ++m) om2[m] = 0ULL;
    #pragma unroll
    for (int ky = 0; ky < 3; ++ky) {
        int yy = i + (ky - 1) * 3;
        if (yy < 0 || yy >= Hh) continue;
        #pragma unroll
        for (int kx = 0; kx < 3; ++kx) {
            int xx = j + (kx - 1) * 3;
            if (xx < 0 || xx >= Ww) continue;
            ull v2 = hpu[yy * Ww + xx];
            const ull* wp = &wof2[(ky * 3 + kx) * 27];
            #pragma unroll
            for (int m = 0; m < 27; ++m) om2[m] = fma2(v2, wp[m], om2[m]);
        }
    }
    float om[27];
    #pragma unroll
    for (int m = 0; m < 27; ++m) { float a, b; unpack2(om2[m], a, b); om[m] = a + b; }

    // modulated deformable conv
    ull outA = 0ULL, outB = 0ULL;
    #pragma unroll
    for (int k = 0; k < 9; ++k) {
        float dyv = om[2 * k];
        float dxv = om[2 * k + 1];
        float mmv = 1.f / (1.f + __expf(-om[18 + k]));
        float py = dyv + (float)((k / 3 - 1) * 3 + i);
        float px = dxv + (float)((k % 3 - 1) * 3 + j);
        float y0f = floorf(py), x0f = floorf(px);
        int y0 = (int)y0f, x0 = (int)x0f;
        float ly = py - y0f, lx = px - x0f;
        float w00 = (1.f - ly) * (1.f - lx);
        float w01 = (1.f - ly) * lx;
        float w10 = ly * (1.f - lx);
        float w11 = ly * lx;
        ull s2 = 0ULL;
        bool xv0 = (x0 >= 0) && (x0 < Ww);
        bool xv1 = (x0 + 1 >= 0) && (x0 + 1 < Ww);
        if (y0 >= 0 && y0 < Hh) {
            const ull* row = hpu + y0 * Ww;
            if (xv0) s2 = fma2(row[x0],     pack2dup(w00), s2);
            if (xv1) s2 = fma2(row[x0 + 1], pack2dup(w01), s2);
        }
        if (y0 + 1 >= 0 && y0 + 1 < Hh) {
            const ull* row = hpu + (y0 + 1) * Ww;
            if (xv0) s2 = fma2(row[x0],     pack2dup(w10), s2);
            if (xv1) s2 = fma2(row[x0 + 1], pack2dup(w11), s2);
        }
        s2 = mul2(s2, pack2dup(mmv));
        outA = fma2(s2, wdA[k], outA);
        outB = fma2(s2, wdB[k], outB);
    }
    float a0, a1, c0, c1;
    unpack2(outA, a0, a1); unpack2(outB, c0, c1);
    float out0 = bds[0] + a0 + a1;
    float out1 = bds[1] + c0 + c1;

    // 1x1 conv + relu
    float r0 = fmaxf(out0 * w2s[0] + out1 * w2s[1] + b2s[0], 0.f);
    float r1 = fmaxf(out0 * w2s[2] + out1 * w2s[3] + b2s[1], 0.f);

    // 2x2 maxpool: lanes {4c,4c+1,4c+2,4c+3} = quad (rows via bit0, col pair via bit1)
    r0 = fmaxf(r0, __shfl_xor_sync(0xffffffffu, r0, 1));
    r0 = fmaxf(r0, __shfl_xor_sync(0xffffffffu, r0, 2));
    r1 = fmaxf(r1, __shfl_xor_sync(0xffffffffu, r1, 1));
    r1 = fmaxf(r1, __shfl_xor_sync(0xffffffffu, r1, 2));

    // pack pooled-col pairs (c even, c odd) -> bf16 hi/lo; partner at lane+4
    float p0 = __shfl_down_sync(0xffffffffu, r0, 4);
    float p1 = __shfl_down_sync(0xffffffffu, r1, 4);
    int c = tid >> 2;                 // pooled col 0..63
    if ((tid & 7) == 0) {
        int kp = pi * 32 + (c >> 1);  // 0..2047 within channel
        size_t base = (size_t)n * 4096;
        g_b1H[base + kp]        = pack_bf16(r0, p0);
        g_b1L[base + kp]        = pack_bf16(bf16_res(r0), bf16_res(p0));
        g_b1H[base + 2048 + kp] = pack_bf16(r1, p1);
        g_b1L[base + 2048 + kp] = pack_bf16(bf16_res(r1), bf16_res(p1));
    }
}

// ---------------- bf16-split FC GEMM ----------------
template<int KFULL, int BSTR, int KSLICE, int MTOT, int SEL>
__global__ __launch_bounds__(256, 1) void fc_mma_bf16(const float* __restrict__ W)
{
    constexpr int NCH = KSLICE / 32;
    __shared__ u32 WsH[64 * 20], WsL[64 * 20];
    __shared__ u32 BsH[128 * 20], BsL[128 * 20];

    const u32* __restrict__ BHg = (SEL == 0) ? g_b1H : g_b2H;
    const u32* __restrict__ BLg = (SEL == 0) ? g_b1L : g_b2L;
    float* __restrict__ part    = (SEL == 0) ? g_part1 : g_part2;

    int tid = threadIdx.x, warp = tid >> 5, lane = tid & 31;
    int g = lane >> 2, tq = lane & 3;
    int wm = warp >> 1, wn = warp & 1;
    int o0 = blockIdx.x * 64, ks = blockIdx.y;
    const float* Wb = W + (size_t)o0 * KFULL + (size_t)ks * KSLICE;
    int bko = ks * (KSLICE / 2);

    int wo = tid >> 2, wseg = tid & 3;
    int bn = tid >> 1, bw = tid & 1;
    const u32* Bsrc = bw ? BLg : BHg;
    u32* Bdst = bw ? BsL : BsH;

    float wreg[8];
    uint4 breg[4];

    float acc[8][4];
    #pragma unroll
    for (int i = 0; i < 8; ++i) { acc[i][0] = acc[i][1] = acc[i][2] = acc[i][3] = 0.f; }

    auto LDG = [&](int c) {
        const float4* wp = (const float4*)(Wb + (size_t)wo * KFULL + c * 32 + wseg * 8);
        float4 w0 = wp[0], w1 = wp[1];
        wreg[0] = w0.x; wreg[1] = w0.y; wreg[2] = w0.z; wreg[3] = w0.w;
        wreg[4] = w1.x; wreg[5] = w1.y; wreg[6] = w1.z; wreg[7] = w1.w;
        const uint4* bp = (const uint4*)(Bsrc + (size_t)bn * BSTR + bko + c * 16);
        breg[0] = bp[0]; breg[1] = bp[1]; breg[2] = bp[2]; breg[3] = bp[3];
    };
    auto STS = [&]() {
        u32 h[4], l[4];
        #pragma unroll
        for (int i = 0; i < 4; ++i) {
            h[i] = pack_bf16(wreg[2 * i], wreg[2 * i + 1]);
            l[i] = pack_bf16(bf16_res(wreg[2 * i]), bf16_res(wreg[2 * i + 1]));
        }
        *(uint4*)(WsH + wo * 20 + wseg * 4) = make_uint4(h[0], h[1], h[2], h[3]);
        *(uint4*)(WsL + wo * 20 + wseg * 4) = make_uint4(l[0], l[1], l[2], l[3]);
        uint4* bd = (uint4*)(Bdst + bn * 20);
        bd[0] = breg[0]; bd[1] = breg[1]; bd[2] = breg[2]; bd[3] = breg[3];
    };
    auto COMPUTE = [&]() {
        #pragma unroll
        for (int s = 0; s < 2; ++s) {
            int kp = s * 8 + tq;
            int ro = (16 * wm + g) * 20;
            u32 ah0 = WsH[ro + kp],       ah1 = WsH[ro + 160 + kp];
            u32 ah2 = WsH[ro + kp + 4],   ah3 = WsH[ro + 160 + kp + 4];
            u32 al0 = WsL[ro + kp],       al1 = WsL[ro + 160 + kp];
            u32 al2 = WsL[ro + kp + 4],   al3 = WsL[ro + 160 + kp + 4];
            #pragma unroll
            for (int nt = 0; nt < 8; ++nt) {
                int rn = (64 * wn + 8 * nt + g) * 20;
                u32 bh0 = BsH[rn + kp], bh1 = BsH[rn + kp + 4];
                u32 bl0 = BsL[rn + kp], bl1 = BsL[rn + kp + 4];
                mma_bf16(acc[nt], ah0, ah1, ah2, ah3, bh0, bh1);
                mma_bf16(acc[nt], ah0, ah1, ah2, ah3, bl0, bl1);
                mma_bf16(acc[nt], al0, al1, al2, al3, bh0, bh1);
            }
        }
    };

    LDG(0); STS();
    __syncthreads();
    if (NCH > 1) LDG(1);

    for (int c = 0; c < NCH; ++c) {
        COMPUTE();
        __syncthreads();
        if (c + 1 < NCH) STS();
        if (c + 2 < NCH) LDG(c + 2);
        __syncthreads();
    }

    int oL = o0 + 16 * wm + g;
    float* pbase = part + (size_t)ks * MTOT * 128;
    #pragma unroll
    for (int nt = 0; nt < 8; ++nt) {
        int n = 64 * wn + 8 * nt + 2 * tq;
        *(float2*)(pbase + (size_t)oL * 128 + n)       = make_float2(acc[nt][0], acc[nt][1]);
        *(float2*)(pbase + (size_t)(oL + 8) * 128 + n) = make_float2(acc[nt][2], acc[nt][3]);
    }
}

// ---------------- reduce 1: fc1 partials -> bias+relu -> bf16 hi/lo for fc2 ----------------
__global__ __launch_bounds__(256) void red1_kernel(const float* __restrict__ bias)
{
    int idx = blockIdx.x * 256 + threadIdx.x;
    int n = idx & 127, kp = idx >> 7;
    int o = 2 * kp;
    float v0 = bias[o], v1 = bias[o + 1];
    #pragma unroll
    for (int ks = 0; ks < 4; ++ks) {
        v0 += g_part1[((size_t)ks * 2048 + o) * 128 + n];
        v1 += g_part1[((size_t)ks * 2048 + o + 1) * 128 + n];
    }
    v0 = fmaxf(v0, 0.f); v1 = fmaxf(v1, 0.f);
    g_b2H[(size_t)n * 1024 + kp] = pack_bf16(v0, v1);
    g_b2L[(size_t)n * 1024 + kp] = pack_bf16(bf16_res(v0), bf16_res(v1));
}

// ---------------- reduce 2: fc2 partials -> bias+relu -> a2N [n][o] ----------------
__global__ __launch_bounds__(256) void red2_kernel(const float* __restrict__ bias)
{
    int idx = blockIdx.x * 256 + threadIdx.x;
    int n = idx & 127, o = idx >> 7;
    float v = bias[o];
    #pragma unroll
    for (int ks = 0; ks < 8; ++ks)
        v += g_part2[((size_t)ks * 1024 + o) * 128 + n];
    g_a2N[(size_t)n * 1024 + o] = fmaxf(v, 0.f);
}

// ---------------- FC3 + sigmoid: one block per n ----------------
__global__ __launch_bounds__(256) void fc3_kernel(const float* __restrict__ io_w,
                                                  const float* __restrict__ io_b,
                                                  float* __restrict__ out)
{
    __shared__ float red[256];
    int n = blockIdx.x, tid = threadIdx.x;
    float acc = 0.f;
    #pragma unroll 4
    for (int k = tid; k < 1024; k += 256)
        acc += g_a2N[(size_t)n * 1024 + k] * io_w[k];
    red[tid] = acc;
    __syncthreads();
    #pragma unroll
    for (int s = 128; s > 0; s >>= 1) {
        if (tid < s) red[tid] += red[tid + s];
        __syncthreads();
    }
    if (tid == 0) out[n] = 1.f / (1.f + __expf(-(red[0] + io_b[0])));
}

// ---------------- launch ----------------
extern "C" void kernel_launch(void* const* d_in, const int* in_sizes, int n_in,
                              void* d_out, int out_size)
{
    const float* mask  = (const float*)d_in[0];
    const float* x     = (const float*)d_in[1];
    const float* w1    = (const float*)d_in[2];
    const float* b1    = (const float*)d_in[3];
    const float* w_off = (const float*)d_in[4];
    const float* w_dcn = (const float*)d_in[5];
    const float* b_dcn = (const float*)d_in[6];
    const float* w2    = (const float*)d_in[7];
    const float* b2    = (const float*)d_in[8];
    const float* fc1_w = (const float*)d_in[9];
    const float* fc1_b = (const float*)d_in[10];
    const float* fc2_w = (const float*)d_in[11];
    const float* fc2_b = (const float*)d_in[12];
    const float* io_w  = (const float*)d_in[13];
    const float* io_b  = (const float*)d_in[14];
    float* out = (float*)d_out;

    // slots #1-#2: dummies so ncu's capture slot (#4) lands on dcn_kernel
    warm_kernel<<<1, 32>>>(0);
    warm_kernel<<<1, 32>>>(1);

    dim3 g1(32, Nn);
    conv1_kernel<<<g1, 128>>>(x, mask, w1, b1);        // #3

    dim3 g2(64, Nn);
    dcn_kernel<<<g2, 256>>>(w_off, w_dcn, b_dcn, w2, b2);  // #4 <- profiled

    fc_mma_bf16<8192, 4096, 2048, 2048, 0><<<dim3(32, 4), 256>>>(fc1_w);
    red1_kernel<<<512, 256>>>(fc1_b);

    fc_mma_bf16<2048, 1024, 256, 1024, 1><<<dim3(16, 8), 256>>>(fc2_w);
    red2_kernel<<<512, 256>>>(fc2_b);

    fc3_kernel<<<128, 256>>>(io_w, io_b, out);
}

// round 10
// speedup vs baseline: 1.6138x; 1.0978x over previous
#include <cuda_runtime.h>
#include <cuda_bf16.h>
#include <math.h>

#define Nn 128
#define Hh 128
#define Ww 128
typedef unsigned long long ull;
typedef unsigned int u32;

// ---------------- device scratch (allocation-free) ----------------
__device__ __align__(16) float2 g_h2[Nn * Hh * Ww];     // conv1 out, channel-interleaved
__device__ __align__(16) float2 g_r2[Nn * Hh * Ww];     // dcn+1x1+relu out, (r0,r1)
__device__ __align__(16) u32   g_b1H[128 * 4096];       // fc1 input, bf16 hi, [n][kp]
__device__ __align__(16) u32   g_b1L[128 * 4096];       // fc1 input, bf16 lo
__device__ __align__(16) float g_part1[4 * 2048 * 128]; // fc1 partials [ks][o][n]
__device__ __align__(16) u32   g_b2H[128 * 1024];       // fc2 input hi, [n][kp]
__device__ __align__(16) u32   g_b2L[128 * 1024];       // fc2 input lo
__device__ __align__(16) float g_part2[8 * 1024 * 128]; // fc2 partials [ks][o][n]
__device__ __align__(16) float g_a2N[128 * 1024];       // fc2 out, [n][o]
__device__ float g_dummy[32];

// ---------------- f32x2 helpers ----------------
__device__ __forceinline__ ull pack2(float lo, float hi) {
    ull r; asm("mov.b64 %0, {%1, %2};" : "=l"(r) : "f"(lo), "f"(hi)); return r;
}
__device__ __forceinline__ ull pack2dup(float v) {
    ull r; asm("mov.b64 %0, {%1, %1};" : "=l"(r) : "f"(v)); return r;
}
__device__ __forceinline__ void unpack2(ull v, float& a, float& b) {
    asm("mov.b64 {%0, %1}, %2;" : "=f"(a), "=f"(b) : "l"(v));
}
__device__ __forceinline__ ull fma2(ull a, ull b, ull c) {
    ull d; asm("fma.rn.f32x2 %0, %1, %2, %3;" : "=l"(d) : "l"(a), "l"(b), "l"(c)); return d;
}
__device__ __forceinline__ ull mul2(ull a, ull b) {
    ull d; asm("mul.rn.f32x2 %0, %1, %2;" : "=l"(d) : "l"(a), "l"(b)); return d;
}

// ---------------- bf16 split helpers ----------------
__device__ __forceinline__ u32 pack_bf16(float a, float b) {
    __nv_bfloat162 h; h.x = __float2bfloat16(a); h.y = __float2bfloat16(b);
    return *reinterpret_cast<u32*>(&h);
}
__device__ __forceinline__ float bf16_res(float v) {
    return v - __bfloat162float(__float2bfloat16(v));
}
__device__ __forceinline__ void mma_bf16(float c[4],
    u32 a0, u32 a1, u32 a2, u32 a3, u32 b0, u32 b1)
{
    asm volatile(
        "mma.sync.aligned.m16n8k16.row.col.f32.bf16.bf16.f32 "
        "{%0,%1,%2,%3}, {%4,%5,%6,%7}, {%8,%9}, {%0,%1,%2,%3};\n"
        : "+f"(c[0]), "+f"(c[1]), "+f"(c[2]), "+f"(c[3])
        : "r"(a0), "r"(a1), "r"(a2), "r"(a3), "r"(b0), "r"(b1));
}

// ---------------- dummy kernels (shift ncu capture slot onto dcn) ----------------
__global__ void warm_kernel(int v) {
    if (threadIdx.x < 32) g_dummy[threadIdx.x] = (float)v;
}

// ---------------- kernel 1: conv3x3 (9ch -> 2ch), pad 1, 4 px/thread ----------------
__global__ __launch_bounds__(128) void conv1_kernel(
    const float* __restrict__ x, const float* __restrict__ mask,
    const float* __restrict__ w1, const float* __restrict__ b1)
{
    __shared__ ull ws2[81];
    int tid = threadIdx.x;
    if (tid < 81) ws2[tid] = pack2(w1[tid], w1[81 + tid]);
    __syncthreads();

    int r = tid >> 5, q = tid & 31;
    int i = blockIdx.x * 4 + r;
    int j0 = q * 4;
    int n = blockIdx.y;

    ull acc[4];
    ull binit = pack2(b1[0], b1[1]);
    #pragma unroll
    for (int p = 0; p < 4; ++p) acc[p] = binit;

    #pragma unroll
    for (int c = 0; c < 9; ++c) {
        const float* src = (c < 8) ? (x + (size_t)(n * 8 + c) * Hh * Ww)
                                   : (mask + (size_t)n * Hh * Ww);
        #pragma unroll
        for (int ky = 0; ky < 3; ++ky) {
            int yy = i + ky - 1;
            if (yy < 0 || yy >= Hh) continue;
            const float* row = src + yy * Ww + j0;
            float win[6];
            win[0] = (j0 > 0) ? row[-1] : 0.f;
            float4 v = *(const float4*)row;
            win[1] = v.x; win[2] = v.y; win[3] = v.z; win[4] = v.w;
            win[5] = (j0 < 124) ? row[4] : 0.f;
            #pragma unroll
            for (int kx = 0; kx < 3; ++kx) {
                ull wk = ws2[c * 9 + ky * 3 + kx];
                #pragma unroll
                for (int p = 0; p < 4; ++p)
                    acc[p] = fma2(pack2dup(win[p + kx]), wk, acc[p]);
            }
        }
    }
    #pragma unroll
    for (int p = 0; p < 4; ++p) {
        float a0, a1; unpack2(acc[p], a0, a1);
        g_h2[((size_t)n * Hh + i) * Ww + j0 + p] = make_float2(a0, a1);
    }
}

// ---- kernel 2: fused conv_off (bf16 MMA) + sigmoid + DCN + 1x1 conv + relu ----
// Block = 1 image row (128 px, 128 threads, 4 warps). conv_off as GEMM:
// om[27 x 128px] = W[27x18(pad 32)] . im2col[18(pad 32) x 128px], 2-term bf16 split.
__global__ __launch_bounds__(128) void dcn_kernel(
    const float* __restrict__ w_off,
    const float* __restrict__ w_dcn, const float* __restrict__ b_dcn,
    const float* __restrict__ w2, const float* __restrict__ b2)
{
    __shared__ u32 WsH[32 * 20], WsL[32 * 20];
    __shared__ __align__(16) u32 BsPool[2 * 128 * 20];   // BsH | BsL; later reused as omS
    __shared__ ull wdA[9], wdB[9];
    __shared__ float bds[2], w2s[4], b2s[2];

    int tid = threadIdx.x;
    int n = blockIdx.y, i = blockIdx.x, j = tid;

    u32* BsH = BsPool;
    u32* BsL = BsPool + 128 * 20;
    float* omS = (float*)BsPool;                          // stride 33, 128*33 <= 5120 u32

    // zero the padded weight tiles
    for (int t = tid; t < 640; t += 128) { WsH[t] = 0; WsL[t] = 0; }
    __syncthreads();

    // fill conv_off weights: A[m][kp=tap] = (w_off[m][c0][tap], w_off[m][c1][tap])
    for (int t = tid; t < 243; t += 128) {
        int m = t / 9, tap = t % 9;
        float wa = w_off[m * 18 + tap];
        float wb = w_off[m * 18 + 9 + tap];
        WsH[m * 20 + tap] = pack_bf16(wa, wb);
        WsL[m * 20 + tap] = pack_bf16(bf16_res(wa), bf16_res(wb));
    }
    if (tid < 9) {
        wdA[tid] = pack2(w_dcn[tid],      w_dcn[9 + tid]);
        wdB[tid] = pack2(w_dcn[18 + tid], w_dcn[27 + tid]);
    }
    if (tid < 4) w2s[tid] = w2[tid];
    if (tid < 2) { bds[tid] = b_dcn[tid]; b2s[tid] = b2[tid]; }

    // im2col: B[kp=tap][n=j] = (h0, h1) at dilated tap, zero-padded
    const float2* hp = g_h2 + (size_t)n * Hh * Ww;
    #pragma unroll
    for (int tap = 0; tap < 9; ++tap) {
        int yy = i + (tap / 3 - 1) * 3;
        int xx = j + (tap % 3 - 1) * 3;
        float2 v = make_float2(0.f, 0.f);
        if ((unsigned)yy < 128u && (unsigned)xx < 128u) v = hp[yy * 128 + xx];
        BsH[j * 20 + tap] = pack_bf16(v.x, v.y);
        BsL[j * 20 + tap] = pack_bf16(bf16_res(v.x), bf16_res(v.y));
    }
    #pragma unroll
    for (int kp = 9; kp < 16; ++kp) { BsH[j * 20 + kp] = 0; BsL[j * 20 + kp] = 0; }
    __syncthreads();

    // MMA: 4 warps split n (32 px each); m-tiles 2 (m 0..31); k-steps 2
    int warp = tid >> 5, lane = tid & 31, g = lane >> 2, tq = lane & 3;
    float acc[2][4][4];
    #pragma unroll
    for (int mt = 0; mt < 2; ++mt)
        #pragma unroll
        for (int nt = 0; nt < 4; ++nt)
            { acc[mt][nt][0] = acc[mt][nt][1] = acc[mt][nt][2] = acc[mt][nt][3] = 0.f; }

    #pragma unroll
    for (int s = 0; s < 2; ++s) {
        int kp = s * 8 + tq;
        #pragma unroll
        for (int mt = 0; mt < 2; ++mt) {
            int ro = (mt * 16 + g) * 20;
            u32 ah0 = WsH[ro + kp],       ah1 = WsH[ro + 160 + kp];
            u32 ah2 = WsH[ro + kp + 4],   ah3 = WsH[ro + 160 + kp + 4];
            u32 al0 = WsL[ro + kp],       al1 = WsL[ro + 160 + kp];
            u32 al2 = WsL[ro + kp + 4],   al3 = WsL[ro + 160 + kp + 4];
            #pragma unroll
            for (int nt = 0; nt < 4; ++nt) {
                int rn = (warp * 32 + nt * 8 + g) * 20;
                u32 bh0 = BsH[rn + kp], bh1 = BsH[rn + kp + 4];
                u32 bl0 = BsL[rn + kp], bl1 = BsL[rn + kp + 4];
                mma_bf16(acc[mt][nt], ah0, ah1, ah2, ah3, bh0, bh1);
                mma_bf16(acc[mt][nt], ah0, ah1, ah2, ah3, bl0, bl1);
                mma_bf16(acc[mt][nt], al0, al1, al2, al3, bh0, bh1);
            }
        }
    }
    __syncthreads();   // all warps done reading Bs before omS overwrites it

    // scatter om fragments to smem: omS[n][m], stride 33 (conflict-free readback)
    #pragma unroll
    for (int mt = 0; mt < 2; ++mt)
        #pragma unroll
        for (int nt = 0; nt < 4; ++nt) {
            int nn = warp * 32 + nt * 8 + 2 * tq;
            int m = mt * 16 + g;
            omS[nn * 33 + m]            = acc[mt][nt][0];
            omS[(nn + 1) * 33 + m]      = acc[mt][nt][1];
            omS[nn * 33 + m + 8]        = acc[mt][nt][2];
            omS[(nn + 1) * 33 + m + 8]  = acc[mt][nt][3];
        }
    __syncthreads();

    // ---- phase B: modulated deformable conv + 1x1 + relu ----
    float om[27];
    #pragma unroll
    for (int m = 0; m < 27; ++m) om[m] = omS[j * 33 + m];

    const ull* hpu = (const ull*)hp;
    ull outA = 0ULL, outB = 0ULL;
    #pragma unroll
    for (int k = 0; k < 9; ++k) {
        float dyv = om[2 * k];
        float dxv = om[2 * k + 1];
        float mmv = 1.f / (1.f + __expf(-om[18 + k]));
        float py = dyv + (float)((k / 3 - 1) * 3 + i);
        float px = dxv + (float)((k % 3 - 1) * 3 + j);
        float y0f = floorf(py), x0f = floorf(px);
        int y0 = (int)y0f, x0 = (int)x0f;
        float ly = py - y0f, lx = px - x0f;
        float w00 = (1.f - ly) * (1.f - lx);
        float w01 = (1.f - ly) * lx;
        float w10 = ly * (1.f - lx);
        float w11 = ly * lx;
        ull s2 = 0ULL;
        bool xv0 = (unsigned)x0 < 128u;
        bool xv1 = (unsigned)(x0 + 1) < 128u;
        if ((unsigned)y0 < 128u) {
            const ull* row = hpu + y0 * Ww;
            if (xv0) s2 = fma2(row[x0],     pack2dup(w00), s2);
            if (xv1) s2 = fma2(row[x0 + 1], pack2dup(w01), s2);
        }
        if ((unsigned)(y0 + 1) < 128u) {
            const ull* row = hpu + (y0 + 1) * Ww;
            if (xv0) s2 = fma2(row[x0],     pack2dup(w10), s2);
            if (xv1) s2 = fma2(row[x0 + 1], pack2dup(w11), s2);
        }
        s2 = mul2(s2, pack2dup(mmv));
        outA = fma2(s2, wdA[k], outA);
        outB = fma2(s2, wdB[k], outB);
    }
    float a0, a1, c0, c1;
    unpack2(outA, a0, a1); unpack2(outB, c0, c1);
    float out0 = bds[0] + a0 + a1;
    float out1 = bds[1] + c0 + c1;

    float r0 = fmaxf(out0 * w2s[0] + out1 * w2s[1] + b2s[0], 0.f);
    float r1 = fmaxf(out0 * w2s[2] + out1 * w2s[3] + b2s[1], 0.f);
    g_r2[((size_t)n * Hh + i) * Ww + j] = make_float2(r0, r1);
}

// ---------------- kernel 2b: 2x2 maxpool + bf16 hi/lo pack for fc1 ----------------
__global__ __launch_bounds__(256) void pool_kernel()
{
    int tid = threadIdx.x;
    int n = blockIdx.y;
    int pr = blockIdx.x * 4 + (tid >> 6);   // pooled row 0..63
    int pc = tid & 63;                      // pooled col 0..63

    const float2* base = g_r2 + (size_t)n * Hh * Ww;
    float2 a = base[(2 * pr) * Ww + 2 * pc];
    float2 b = base[(2 * pr) * Ww + 2 * pc + 1];
    float2 c = base[(2 * pr + 1) * Ww + 2 * pc];
    float2 d = base[(2 * pr + 1) * Ww + 2 * pc + 1];
    float r0 = fmaxf(fmaxf(a.x, b.x), fmaxf(c.x, d.x));
    float r1 = fmaxf(fmaxf(a.y, b.y), fmaxf(c.y, d.y));

    // pack (pc even, pc odd) pairs; partner at lane+1
    float p0 = __shfl_down_sync(0xffffffffu, r0, 1);
    float p1 = __shfl_down_sync(0xffffffffu, r1, 1);
    if (!(tid & 1)) {
        int kp = pr * 32 + (pc >> 1);       // 0..2047 within channel
        size_t bo = (size_t)n * 4096;
        g_b1H[bo + kp]        = pack_bf16(r0, p0);
        g_b1L[bo + kp]        = pack_bf16(bf16_res(r0), bf16_res(p0));
        g_b1H[bo + 2048 + kp] = pack_bf16(r1, p1);
        g_b1L[bo + 2048 + kp] = pack_bf16(bf16_res(r1), bf16_res(p1));
    }
}

// ---------------- bf16-split FC GEMM ----------------
template<int KFULL, int BSTR, int KSLICE, int MTOT, int SEL>
__global__ __launch_bounds__(256, 1) void fc_mma_bf16(const float* __restrict__ W)
{
    constexpr int NCH = KSLICE / 32;
    __shared__ u32 WsH[64 * 20], WsL[64 * 20];
    __shared__ u32 BsH[128 * 20], BsL[128 * 20];

    const u32* __restrict__ BHg = (SEL == 0) ? g_b1H : g_b2H;
    const u32* __restrict__ BLg = (SEL == 0) ? g_b1L : g_b2L;
    float* __restrict__ part    = (SEL == 0) ? g_part1 : g_part2;

    int tid = threadIdx.x, warp = tid >> 5, lane = tid & 31;
    int g = lane >> 2, tq = lane & 3;
    int wm = warp >> 1, wn = warp & 1;
    int o0 = blockIdx.x * 64, ks = blockIdx.y;
    const float* Wb = W + (size_t)o0 * KFULL + (size_t)ks * KSLICE;
    int bko = ks * (KSLICE / 2);

    int wo = tid >> 2, wseg = tid & 3;
    int bn = tid >> 1, bw = tid & 1;
    const u32* Bsrc = bw ? BLg : BHg;
    u32* Bdst = bw ? BsL : BsH;

    float wreg[8];
    uint4 breg[4];

    float acc[8][4];
    #pragma unroll
    for (int i = 0; i < 8; ++i) { acc[i][0] = acc[i][1] = acc[i][2] = acc[i][3] = 0.f; }

    auto LDG = [&](int c) {
        const float4* wp = (const float4*)(Wb + (size_t)wo * KFULL + c * 32 + wseg * 8);
        float4 w0 = wp[0], w1 = wp[1];
        wreg[0] = w0.x; wreg[1] = w0.y; wreg[2] = w0.z; wreg[3] = w0.w;
        wreg[4] = w1.x; wreg[5] = w1.y; wreg[6] = w1.z; wreg[7] = w1.w;
        const uint4* bp = (const uint4*)(Bsrc + (size_t)bn * BSTR + bko + c * 16);
        breg[0] = bp[0]; breg[1] = bp[1]; breg[2] = bp[2]; breg[3] = bp[3];
    };
    auto STS = [&]() {
        u32 h[4], l[4];
        #pragma unroll
        for (int i = 0; i < 4; ++i) {
            h[i] = pack_bf16(wreg[2 * i], wreg[2 * i + 1]);
            l[i] = pack_bf16(bf16_res(wreg[2 * i]), bf16_res(wreg[2 * i + 1]));
        }
        *(uint4*)(WsH + wo * 20 + wseg * 4) = make_uint4(h[0], h[1], h[2], h[3]);
        *(uint4*)(WsL + wo * 20 + wseg * 4) = make_uint4(l[0], l[1], l[2], l[3]);
        uint4* bd = (uint4*)(Bdst + bn * 20);
        bd[0] = breg[0]; bd[1] = breg[1]; bd[2] = breg[2]; bd[3] = breg[3];
    };
    auto COMPUTE = [&]() {
        #pragma unroll
        for (int s = 0; s < 2; ++s) {
            int kp = s * 8 + tq;
            int ro = (16 * wm + g) * 20;
            u32 ah0 = WsH[ro + kp],       ah1 = WsH[ro + 160 + kp];
            u32 ah2 = WsH[ro + kp + 4],   ah3 = WsH[ro + 160 + kp + 4];
            u32 al0 = WsL[ro + kp],       al1 = WsL[ro + 160 + kp];
            u32 al2 = WsL[ro + kp + 4],   al3 = WsL[ro + 160 + kp + 4];
            #pragma unroll
            for (int nt = 0; nt < 8; ++nt) {
                int rn = (64 * wn + 8 * nt + g) * 20;
                u32 bh0 = BsH[rn + kp], bh1 = BsH[rn + kp + 4];
                u32 bl0 = BsL[rn + kp], bl1 = BsL[rn + kp + 4];
                mma_bf16(acc[nt], ah0, ah1, ah2, ah3, bh0, bh1);
                mma_bf16(acc[nt], ah0, ah1, ah2, ah3, bl0, bl1);
                mma_bf16(acc[nt], al0, al1, al2, al3, bh0, bh1);
            }
        }
    };

    LDG(0); STS();
    __syncthreads();
    if (NCH > 1) LDG(1);

    for (int c = 0; c < NCH; ++c) {
        COMPUTE();
        __syncthreads();
        if (c + 1 < NCH) STS();
        if (c + 2 < NCH) LDG(c + 2);
        __syncthreads();
    }

    int oL = o0 + 16 * wm + g;
    float* pbase = part + (size_t)ks * MTOT * 128;
    #pragma unroll
    for (int nt = 0; nt < 8; ++nt) {
        int n = 64 * wn + 8 * nt + 2 * tq;
        *(float2*)(pbase + (size_t)oL * 128 + n)       = make_float2(acc[nt][0], acc[nt][1]);
        *(float2*)(pbase + (size_t)(oL + 8) * 128 + n) = make_float2(acc[nt][2], acc[nt][3]);
    }
}

// ---------------- reduce 1: fc1 partials -> bias+relu -> bf16 hi/lo for fc2 ----------------
__global__ __launch_bounds__(256) void red1_kernel(const float* __restrict__ bias)
{
    int idx = blockIdx.x * 256 + threadIdx.x;
    int n = idx & 127, kp = idx >> 7;
    int o = 2 * kp;
    float v0 = bias[o], v1 = bias[o + 1];
    #pragma unroll
    for (int ks = 0; ks < 4; ++ks) {
        v0 += g_part1[((size_t)ks * 2048 + o) * 128 + n];
        v1 += g_part1[((size_t)ks * 2048 + o + 1) * 128 + n];
    }
    v0 = fmaxf(v0, 0.f); v1 = fmaxf(v1, 0.f);
    g_b2H[(size_t)n * 1024 + kp] = pack_bf16(v0, v1);
    g_b2L[(size_t)n * 1024 + kp] = pack_bf16(bf16_res(v0), bf16_res(v1));
}

// ---------------- reduce 2: fc2 partials -> bias+relu -> a2N [n][o] ----------------
__global__ __launch_bounds__(256) void red2_kernel(const float* __restrict__ bias)
{
    int idx = blockIdx.x * 256 + threadIdx.x;
    int n = idx & 127, o = idx >> 7;
    float v = bias[o];
    #pragma unroll
    for (int ks = 0; ks < 8; ++ks)
        v += g_part2[((size_t)ks * 1024 + o) * 128 + n];
    g_a2N[(size_t)n * 1024 + o] = fmaxf(v, 0.f);
}

// ---------------- FC3 + sigmoid: one block per n ----------------
__global__ __launch_bounds__(256) void fc3_kernel(const float* __restrict__ io_w,
                                                  const float* __restrict__ io_b,
                                                  float* __restrict__ out)
{
    __shared__ float red[256];
    int n = blockIdx.x, tid = threadIdx.x;
    float acc = 0.f;
    #pragma unroll 4
    for (int k = tid; k < 1024; k += 256)
        acc += g_a2N[(size_t)n * 1024 + k] * io_w[k];
    red[tid] = acc;
    __syncthreads();
    #pragma unroll
    for (int s = 128; s > 0; s >>= 1) {
        if (tid < s) red[tid] += red[tid + s];
        __syncthreads();
    }
    if (tid == 0) out[n] = 1.f / (1.f + __expf(-(red[0] + io_b[0])));
}

// ---------------- launch ----------------
extern "C" void kernel_launch(void* const* d_in, const int* in_sizes, int n_in,
                              void* d_out, int out_size)
{
    const float* mask  = (const float*)d_in[0];
    const float* x     = (const float*)d_in[1];
    const float* w1    = (const float*)d_in[2];
    const float* b1    = (const float*)d_in[3];
    const float* w_off = (const float*)d_in[4];
    const float* w_dcn = (const float*)d_in[5];
    const float* b_dcn = (const float*)d_in[6];
    const float* w2    = (const float*)d_in[7];
    const float* b2    = (const float*)d_in[8];
    const float* fc1_w = (const float*)d_in[9];
    const float* fc1_b = (const float*)d_in[10];
    const float* fc2_w = (const float*)d_in[11];
    const float* fc2_b = (const float*)d_in[12];
    const float* io_w  = (const float*)d_in[13];
    const float* io_b  = (const float*)d_in[14];
    float* out = (float*)d_out;

    // slots #1-#2: dummies so ncu's capture slot (#4) lands on dcn_kernel
    warm_kernel<<<1, 32>>>(0);
    warm_kernel<<<1, 32>>>(1);

    dim3 g1(32, Nn);
    conv1_kernel<<<g1, 128>>>(x, mask, w1, b1);            // #3

    dim3 g2(Hh, Nn);
    dcn_kernel<<<g2, 128>>>(w_off, w_dcn, b_dcn, w2, b2);  // #4 <- profiled

    pool_kernel<<<dim3(16, Nn), 256>>>();

    fc_mma_bf16<8192, 4096, 2048, 2048, 0><<<dim3(32, 4), 256>>>(fc1_w);
    red1_kernel<<<512, 256>>>(fc1_b);

    fc_mma_bf16<2048, 1024, 256, 1024, 1><<<dim3(16, 8), 256>>>(fc2_w);
    red2_kernel<<<512, 256>>>(fc2_b);

    fc3_kernel<<<128, 256>>>(io_w, io_b, out);
}

// round 11
// speedup vs baseline: 1.6593x; 1.0282x over previous
#include <cuda_runtime.h>
#include <cuda_bf16.h>
#include <math.h>

#define Nn 128
#define Hh 128
#define Ww 128
typedef unsigned long long ull;
typedef unsigned int u32;

// ---------------- device scratch (allocation-free) ----------------
__device__ __align__(16) float2 g_h2[Nn * Hh * Ww];     // conv1 out, channel-interleaved
__device__ __align__(16) float2 g_r2[Nn * Hh * Ww];     // dcn+1x1+relu out, (r0,r1)
__device__ __align__(16) u32   g_b1H[128 * 4096];       // fc1 input, bf16 hi, [n][kp]
__device__ __align__(16) u32   g_b1L[128 * 4096];       // fc1 input, bf16 lo
__device__ __align__(16) float g_part1[8 * 2048 * 128]; // fc1 partials [ks][o][n]
__device__ __align__(16) u32   g_b2H[128 * 1024];       // fc2 input hi, [n][kp]
__device__ __align__(16) u32   g_b2L[128 * 1024];       // fc2 input lo
__device__ __align__(16) float g_part2[8 * 1024 * 128]; // fc2 partials [ks][o][n]
__device__ __align__(16) float g_a2N[128 * 1024];       // fc2 out, [n][o]
__device__ float g_dummy[32];

// ---------------- f32x2 helpers ----------------
__device__ __forceinline__ ull pack2(float lo, float hi) {
    ull r; asm("mov.b64 %0, {%1, %2};" : "=l"(r) : "f"(lo), "f"(hi)); return r;
}
__device__ __forceinline__ ull pack2dup(float v) {
    ull r; asm("mov.b64 %0, {%1, %1};" : "=l"(r) : "f"(v)); return r;
}
__device__ __forceinline__ void unpack2(ull v, float& a, float& b) {
    asm("mov.b64 {%0, %1}, %2;" : "=f"(a), "=f"(b) : "l"(v));
}
__device__ __forceinline__ ull fma2(ull a, ull b, ull c) {
    ull d; asm("fma.rn.f32x2 %0, %1, %2, %3;" : "=l"(d) : "l"(a), "l"(b), "l"(c)); return d;
}
__device__ __forceinline__ ull mul2(ull a, ull b) {
    ull d; asm("mul.rn.f32x2 %0, %1, %2;" : "=l"(d) : "l"(a), "l"(b)); return d;
}

// ---------------- bf16 split helpers ----------------
__device__ __forceinline__ u32 pack_bf16(float a, float b) {
    __nv_bfloat162 h; h.x = __float2bfloat16(a); h.y = __float2bfloat16(b);
    return *reinterpret_cast<u32*>(&h);
}
__device__ __forceinline__ float bf16_res(float v) {
    return v - __bfloat162float(__float2bfloat16(v));
}
__device__ __forceinline__ void mma_bf16(float c[4],
    u32 a0, u32 a1, u32 a2, u32 a3, u32 b0, u32 b1)
{
    asm volatile(
        "mma.sync.aligned.m16n8k16.row.col.f32.bf16.bf16.f32 "
        "{%0,%1,%2,%3}, {%4,%5,%6,%7}, {%8,%9}, {%0,%1,%2,%3};\n"
        : "+f"(c[0]), "+f"(c[1]), "+f"(c[2]), "+f"(c[3])
        : "r"(a0), "r"(a1), "r"(a2), "r"(a3), "r"(b0), "r"(b1));
}

// ---------------- dummy kernels (shift ncu capture slot onto dcn) ----------------
__global__ void warm_kernel(int v) {
    if (threadIdx.x < 32) g_dummy[threadIdx.x] = (float)v;
}

// ---------------- kernel 1: conv3x3 (9ch -> 2ch), pad 1, 4 px/thread ----------------
__global__ __launch_bounds__(128) void conv1_kernel(
    const float* __restrict__ x, const float* __restrict__ mask,
    const float* __restrict__ w1, const float* __restrict__ b1)
{
    __shared__ ull ws2[81];
    int tid = threadIdx.x;
    if (tid < 81) ws2[tid] = pack2(w1[tid], w1[81 + tid]);
    __syncthreads();

    int r = tid >> 5, q = tid & 31;
    int i = blockIdx.x * 4 + r;
    int j0 = q * 4;
    int n = blockIdx.y;

    ull acc[4];
    ull binit = pack2(b1[0], b1[1]);
    #pragma unroll
    for (int p = 0; p < 4; ++p) acc[p] = binit;

    #pragma unroll
    for (int c = 0; c < 9; ++c) {
        const float* src = (c < 8) ? (x + (size_t)(n * 8 + c) * Hh * Ww)
                                   : (mask + (size_t)n * Hh * Ww);
        #pragma unroll
        for (int ky = 0; ky < 3; ++ky) {
            int yy = i + ky - 1;
            if (yy < 0 || yy >= Hh) continue;
            const float* row = src + yy * Ww + j0;
            float win[6];
            win[0] = (j0 > 0) ? row[-1] : 0.f;
            float4 v = *(const float4*)row;
            win[1] = v.x; win[2] = v.y; win[3] = v.z; win[4] = v.w;
            win[5] = (j0 < 124) ? row[4] : 0.f;
            #pragma unroll
            for (int kx = 0; kx < 3; ++kx) {
                ull wk = ws2[c * 9 + ky * 3 + kx];
                #pragma unroll
                for (int p = 0; p < 4; ++p)
                    acc[p] = fma2(pack2dup(win[p + kx]), wk, acc[p]);
            }
        }
    }
    #pragma unroll
    for (int p = 0; p < 4; ++p) {
        float a0, a1; unpack2(acc[p], a0, a1);
        g_h2[((size_t)n * Hh + i) * Ww + j0 + p] = make_float2(a0, a1);
    }
}

// ---- kernel 2: fused conv_off (bf16 MMA, staged im2col) + sigmoid + DCN + 1x1 + relu ----
// Block = 1 image row (128 px, 128 threads, 4 warps).
// Staging: the 3 dilated rows (i-3, i, i+3), cols -4..131, as bf16 hi/lo in smem (once
// per block). MMA B-fragments load directly from staging with tap-derived addressing.
__global__ __launch_bounds__(128) void dcn_kernel(
    const float* __restrict__ w_off,
    const float* __restrict__ w_dcn, const float* __restrict__ b_dcn,
    const float* __restrict__ w2, const float* __restrict__ b2)
{
    __shared__ u32 WsH[32 * 20], WsL[32 * 20];
    __shared__ __align__(16) u32 stg[4224];   // staging (848 u32) then reused as omS (128*33 f32)
    __shared__ ull wdA[9], wdB[9];
    __shared__ float bds[2], w2s[4], b2s[2];

    int tid = threadIdx.x;
    int n = blockIdx.y, i = blockIdx.x, j = tid;
    int warp = tid >> 5, lane = tid & 31, g = lane >> 2, tq = lane & 3;

    float* omS = (float*)stg;     // stride 33 after staging phase

    // zero padded weight tiles
    for (int t = tid; t < 640; t += 128) { WsH[t] = 0; WsL[t] = 0; }
    __syncthreads();

    // conv_off weights: A[m][kp=tap] = (w_off[m][c0][tap], w_off[m][c1][tap])
    for (int t = tid; t < 243; t += 128) {
        int m = t / 9, tap = t % 9;
        float wa = w_off[m * 18 + tap];
        float wb = w_off[m * 18 + 9 + tap];
        WsH[m * 20 + tap] = pack_bf16(wa, wb);
        WsL[m * 20 + tap] = pack_bf16(bf16_res(wa), bf16_res(wb));
    }
    if (tid < 9) {
        wdA[tid] = pack2(w_dcn[tid],      w_dcn[9 + tid]);
        wdB[tid] = pack2(w_dcn[18 + tid], w_dcn[27 + tid]);
    }
    if (tid < 4) w2s[tid] = w2[tid];
    if (tid < 2) { bds[tid] = b_dcn[tid]; b2s[tid] = b2[tid]; }

    // stage 3 dilated rows: H at stg[0..407], L at stg[408..815], zeros at stg[816..847]
    const float2* hp = g_h2 + (size_t)n * Hh * Ww;
    for (int idx = tid; idx < 408; idx += 128) {
        int r = idx / 136, ic = idx - r * 136;
        int yy = i + (r - 1) * 3, col = ic - 4;
        float2 v = make_float2(0.f, 0.f);
        if ((unsigned)yy < 128u && (unsigned)col < 128u) v = hp[yy * 128 + col];
        stg[idx]       = pack_bf16(v.x, v.y);
        stg[408 + idx] = pack_bf16(bf16_res(v.x), bf16_res(v.y));
    }
    if (tid < 32) stg[816 + tid] = 0;
    __syncthreads();

    // MMA: om[27pad32 x 128px] = W . im2col ; 4 warps split px (32 each)
    float acc[2][4][4];
    #pragma unroll
    for (int mt = 0; mt < 2; ++mt)
        #pragma unroll
        for (int nt = 0; nt < 4; ++nt)
            { acc[mt][nt][0] = acc[mt][nt][1] = acc[mt][nt][2] = acc[mt][nt][3] = 0.f; }

    int colg = warp * 32 + g;
    #pragma unroll
    for (int s = 0; s < 2; ++s) {
        int kp1 = s * 8 + tq;
        int kp2 = kp1 + 4;
        // B base addresses from tap geometry: idx = row*136 + col + 1 + 3*dx
        int bH0, bL0, bH1, bL1;
        if (kp1 < 9) { int r = kp1 / 3, dx = kp1 - 3 * r;
                       int b = r * 136 + 1 + 3 * dx + colg; bH0 = b; bL0 = b + 408; }
        else         { bH0 = 816; bL0 = 816; }
        if (kp2 < 9) { int r = kp2 / 3, dx = kp2 - 3 * r;
                       int b = r * 136 + 1 + 3 * dx + colg; bH1 = b; bL1 = b + 408; }
        else         { bH1 = 816; bL1 = 816; }

        // A fragments (hoisted over nt)
        u32 aH[2][4], aL[2][4];
        #pragma unroll
        for (int mt = 0; mt < 2; ++mt) {
            int ro = (mt * 16 + g) * 20;
            aH[mt][0] = WsH[ro + kp1];       aH[mt][1] = WsH[ro + 160 + kp1];
            aH[mt][2] = WsH[ro + kp1 + 4];   aH[mt][3] = WsH[ro + 160 + kp1 + 4];
            aL[mt][0] = WsL[ro + kp1];       aL[mt][1] = WsL[ro + 160 + kp1];
            aL[mt][2] = WsL[ro + kp1 + 4];   aL[mt][3] = WsL[ro + 160 + kp1 + 4];
        }

        #pragma unroll
        for (int nt = 0; nt < 4; ++nt) {
            int co = nt * 8;
            u32 bh0 = stg[bH0 + co], bh1 = stg[bH1 + co];
            u32 bl0 = stg[bL0 + co], bl1 = stg[bL1 + co];
            #pragma unroll
            for (int mt = 0; mt < 2; ++mt) {
                mma_bf16(acc[mt][nt], aH[mt][0], aH[mt][1], aH[mt][2], aH[mt][3], bh0, bh1);
                mma_bf16(acc[mt][nt], aH[mt][0], aH[mt][1], aH[mt][2], aH[mt][3], bl0, bl1);
                mma_bf16(acc[mt][nt], aL[mt][0], aL[mt][1], aL[mt][2], aL[mt][3], bh0, bh1);
            }
        }
    }
    __syncthreads();   // staging reads done before omS overwrites

    // scatter om fragments: omS[px][m], stride 33
    #pragma unroll
    for (int mt = 0; mt < 2; ++mt)
        #pragma unroll
        for (int nt = 0; nt < 4; ++nt) {
            int nn = warp * 32 + nt * 8 + 2 * tq;
            int m = mt * 16 + g;
            omS[nn * 33 + m]       = acc[mt][nt][0];
            omS[(nn + 1) * 33 + m] = acc[mt][nt][1];
            if (m + 8 < 27) {
                omS[nn * 33 + m + 8]       = acc[mt][nt][2];
                omS[(nn + 1) * 33 + m + 8] = acc[mt][nt][3];
            }
        }
    __syncthreads();

    // ---- phase B: modulated deformable conv + 1x1 + relu ----
    float om[27];
    #pragma unroll
    for (int m = 0; m < 27; ++m) om[m] = omS[j * 33 + m];

    const ull* hpu = (const ull*)hp;
    ull outA = 0ULL, outB = 0ULL;
    #pragma unroll
    for (int k = 0; k < 9; ++k) {
        float dyv = om[2 * k];
        float dxv = om[2 * k + 1];
        float mmv = 1.f / (1.f + __expf(-om[18 + k]));
        float py = dyv + (float)((k / 3 - 1) * 3 + i);
        float px = dxv + (float)((k % 3 - 1) * 3 + j);
        float y0f = floorf(py), x0f = floorf(px);
        int y0 = (int)y0f, x0 = (int)x0f;
        float ly = py - y0f, lx = px - x0f;
        float w00 = (1.f - ly) * (1.f - lx);
        float w01 = (1.f - ly) * lx;
        float w10 = ly * (1.f - lx);
        float w11 = ly * lx;
        ull s2 = 0ULL;
        bool xv0 = (unsigned)x0 < 128u;
        bool xv1 = (unsigned)(x0 + 1) < 128u;
        if ((unsigned)y0 < 128u) {
            const ull* row = hpu + y0 * Ww;
            if (xv0) s2 = fma2(row[x0],     pack2dup(w00), s2);
            if (xv1) s2 = fma2(row[x0 + 1], pack2dup(w01), s2);
        }
        if ((unsigned)(y0 + 1) < 128u) {
            const ull* row = hpu + (y0 + 1) * Ww;
            if (xv0) s2 = fma2(row[x0],     pack2dup(w10), s2);
            if (xv1) s2 = fma2(row[x0 + 1], pack2dup(w11), s2);
        }
        s2 = mul2(s2, pack2dup(mmv));
        outA = fma2(s2, wdA[k], outA);
        outB = fma2(s2, wdB[k], outB);
    }
    float a0, a1, c0, c1;
    unpack2(outA, a0, a1); unpack2(outB, c0, c1);
    float out0 = bds[0] + a0 + a1;
    float out1 = bds[1] + c0 + c1;

    float r0 = fmaxf(out0 * w2s[0] + out1 * w2s[1] + b2s[0], 0.f);
    float r1 = fmaxf(out0 * w2s[2] + out1 * w2s[3] + b2s[1], 0.f);
    g_r2[((size_t)n * Hh + i) * Ww + j] = make_float2(r0, r1);
}

// ---------------- kernel 2b: 2x2 maxpool + bf16 hi/lo pack for fc1 ----------------
__global__ __launch_bounds__(256) void pool_kernel()
{
    int tid = threadIdx.x;
    int n = blockIdx.y;
    int pr = blockIdx.x * 4 + (tid >> 6);   // pooled row 0..63
    int pc = tid & 63;                      // pooled col 0..63

    const float2* base = g_r2 + (size_t)n * Hh * Ww;
    float2 a = base[(2 * pr) * Ww + 2 * pc];
    float2 b = base[(2 * pr) * Ww + 2 * pc + 1];
    float2 c = base[(2 * pr + 1) * Ww + 2 * pc];
    float2 d = base[(2 * pr + 1) * Ww + 2 * pc + 1];
    float r0 = fmaxf(fmaxf(a.x, b.x), fmaxf(c.x, d.x));
    float r1 = fmaxf(fmaxf(a.y, b.y), fmaxf(c.y, d.y));

    float p0 = __shfl_down_sync(0xffffffffu, r0, 1);
    float p1 = __shfl_down_sync(0xffffffffu, r1, 1);
    if (!(tid & 1)) {
        int kp = pr * 32 + (pc >> 1);       // 0..2047 within channel
        size_t bo = (size_t)n * 4096;
        g_b1H[bo + kp]        = pack_bf16(r0, p0);
        g_b1L[bo + kp]        = pack_bf16(bf16_res(r0), bf16_res(p0));
        g_b1H[bo + 2048 + kp] = pack_bf16(r1, p1);
        g_b1L[bo + 2048 + kp] = pack_bf16(bf16_res(r1), bf16_res(p1));
    }
}

// ---------------- bf16-split FC GEMM ----------------
template<int KFULL, int BSTR, int KSLICE, int MTOT, int SEL>
__global__ __launch_bounds__(256, 1) void fc_mma_bf16(const float* __restrict__ W)
{
    constexpr int NCH = KSLICE / 32;
    __shared__ u32 WsH[64 * 20], WsL[64 * 20];
    __shared__ u32 BsH[128 * 20], BsL[128 * 20];

    const u32* __restrict__ BHg = (SEL == 0) ? g_b1H : g_b2H;
    const u32* __restrict__ BLg = (SEL == 0) ? g_b1L : g_b2L;
    float* __restrict__ part    = (SEL == 0) ? g_part1 : g_part2;

    int tid = threadIdx.x, warp = tid >> 5, lane = tid & 31;
    int g = lane >> 2, tq = lane & 3;
    int wm = warp >> 1, wn = warp & 1;
    int o0 = blockIdx.x * 64, ks = blockIdx.y;
    const float* Wb = W + (size_t)o0 * KFULL + (size_t)ks * KSLICE;
    int bko = ks * (KSLICE / 2);

    int wo = tid >> 2, wseg = tid & 3;
    int bn = tid >> 1, bw = tid & 1;
    const u32* Bsrc = bw ? BLg : BHg;
    u32* Bdst = bw ? BsL : BsH;

    float wreg[8];
    uint4 breg[4];

    float acc[8][4];
    #pragma unroll
    for (int i = 0; i < 8; ++i) { acc[i][0] = acc[i][1] = acc[i][2] = acc[i][3] = 0.f; }

    auto LDG = [&](int c) {
        const float4* wp = (const float4*)(Wb + (size_t)wo * KFULL + c * 32 + wseg * 8);
        float4 w0 = wp[0], w1 = wp[1];
        wreg[0] = w0.x; wreg[1] = w0.y; wreg[2] = w0.z; wreg[3] = w0.w;
        wreg[4] = w1.x; wreg[5] = w1.y; wreg[6] = w1.z; wreg[7] = w1.w;
        const uint4* bp = (const uint4*)(Bsrc + (size_t)bn * BSTR + bko + c * 16);
        breg[0] = bp[0]; breg[1] = bp[1]; breg[2] = bp[2]; breg[3] = bp[3];
    };
    auto STS = [&]() {
        u32 h[4], l[4];
        #pragma unroll
        for (int i = 0; i < 4; ++i) {
            h[i] = pack_bf16(wreg[2 * i], wreg[2 * i + 1]);
            l[i] = pack_bf16(bf16_res(wreg[2 * i]), bf16_res(wreg[2 * i + 1]));
        }
        *(uint4*)(WsH + wo * 20 + wseg * 4) = make_uint4(h[0], h[1], h[2], h[3]);
        *(uint4*)(WsL + wo * 20 + wseg * 4) = make_uint4(l[0], l[1], l[2], l[3]);
        uint4* bd = (uint4*)(Bdst + bn * 20);
        bd[0] = breg[0]; bd[1] = breg[1]; bd[2] = breg[2]; bd[3] = breg[3];
    };
    auto COMPUTE = [&]() {
        #pragma unroll
        for (int s = 0; s < 2; ++s) {
            int kp = s * 8 + tq;
            int ro = (16 * wm + g) * 20;
            u32 ah0 = WsH[ro + kp],       ah1 = WsH[ro + 160 + kp];
            u32 ah2 = WsH[ro + kp + 4],   ah3 = WsH[ro + 160 + kp + 4];
            u32 al0 = WsL[ro + kp],       al1 = WsL[ro + 160 + kp];
            u32 al2 = WsL[ro + kp + 4],   al3 = WsL[ro + 160 + kp + 4];
            #pragma unroll
            for (int nt = 0; nt < 8; ++nt) {
                int rn = (64 * wn + 8 * nt + g) * 20;
                u32 bh0 = BsH[rn + kp], bh1 = BsH[rn + kp + 4];
                u32 bl0 = BsL[rn + kp], bl1 = BsL[rn + kp + 4];
                mma_bf16(acc[nt], ah0, ah1, ah2, ah3, bh0, bh1);
                mma_bf16(acc[nt], ah0, ah1, ah2, ah3, bl0, bl1);
                mma_bf16(acc[nt], al0, al1, al2, al3, bh0, bh1);
            }
        }
    };

    LDG(0); STS();
    __syncthreads();
    if (NCH > 1) LDG(1);

    for (int c = 0; c < NCH; ++c) {
        COMPUTE();
        __syncthreads();
        if (c + 1 < NCH) STS();
        if (c + 2 < NCH) LDG(c + 2);
        __syncthreads();
    }

    int oL = o0 + 16 * wm + g;
    float* pbase = part + (size_t)ks * MTOT * 128;
    #pragma unroll
    for (int nt = 0; nt < 8; ++nt) {
        int n = 64 * wn + 8 * nt + 2 * tq;
        *(float2*)(pbase + (size_t)oL * 128 + n)       = make_float2(acc[nt][0], acc[nt][1]);
        *(float2*)(pbase + (size_t)(oL + 8) * 128 + n) = make_float2(acc[nt][2], acc[nt][3]);
    }
}

// ---------------- reduce 1: fc1 partials -> bias+relu -> bf16 hi/lo for fc2 ----------------
__global__ __launch_bounds__(256) void red1_kernel(const float* __restrict__ bias)
{
    int idx = blockIdx.x * 256 + threadIdx.x;
    int n = idx & 127, kp = idx >> 7;
    int o = 2 * kp;
    float v0 = bias[o], v1 = bias[o + 1];
    #pragma unroll
    for (int ks = 0; ks < 8; ++ks) {
        v0 += g_part1[((size_t)ks * 2048 + o) * 128 + n];
        v1 += g_part1[((size_t)ks * 2048 + o + 1) * 128 + n];
    }
    v0 = fmaxf(v0, 0.f); v1 = fmaxf(v1, 0.f);
    g_b2H[(size_t)n * 1024 + kp] = pack_bf16(v0, v1);
    g_b2L[(size_t)n * 1024 + kp] = pack_bf16(bf16_res(v0), bf16_res(v1));
}

// ---------------- reduce 2: fc2 partials -> bias+relu -> a2N [n][o] ----------------
__global__ __launch_bounds__(256) void red2_kernel(const float* __restrict__ bias)
{
    int idx = blockIdx.x * 256 + threadIdx.x;
    int n = idx & 127, o = idx >> 7;
    float v = bias[o];
    #pragma unroll
    for (int ks = 0; ks < 8; ++ks)
        v += g_part2[((size_t)ks * 1024 + o) * 128 + n];
    g_a2N[(size_t)n * 1024 + o] = fmaxf(v, 0.f);
}

// ---------------- FC3 + sigmoid: one block per n ----------------
__global__ __launch_bounds__(256) void fc3_kernel(const float* __restrict__ io_w,
                                                  const float* __restrict__ io_b,
                                                  float* __restrict__ out)
{
    __shared__ float red[256];
    int n = blockIdx.x, tid = threadIdx.x;
    float acc = 0.f;
    #pragma unroll 4
    for (int k = tid; k < 1024; k += 256)
        acc += g_a2N[(size_t)n * 1024 + k] * io_w[k];
    red[tid] = acc;
    __syncthreads();
    #pragma unroll
    for (int s = 128; s > 0; s >>= 1) {
        if (tid < s) red[tid] += red[tid + s];
        __syncthreads();
    }
    if (tid == 0) out[n] = 1.f / (1.f + __expf(-(red[0] + io_b[0])));
}

// ---------------- launch ----------------
extern "C" void kernel_launch(void* const* d_in, const int* in_sizes, int n_in,
                              void* d_out, int out_size)
{
    const float* mask  = (const float*)d_in[0];
    const float* x     = (const float*)d_in[1];
    const float* w1    = (const float*)d_in[2];
    const float* b1    = (const float*)d_in[3];
    const float* w_off = (const float*)d_in[4];
    const float* w_dcn = (const float*)d_in[5];
    const float* b_dcn = (const float*)d_in[6];
    const float* w2    = (const float*)d_in[7];
    const float* b2    = (const float*)d_in[8];
    const float* fc1_w = (const float*)d_in[9];
    const float* fc1_b = (const float*)d_in[10];
    const float* fc2_w = (const float*)d_in[11];
    const float* fc2_b = (const float*)d_in[12];
    const float* io_w  = (const float*)d_in[13];
    const float* io_b  = (const float*)d_in[14];
    float* out = (float*)d_out;

    // slots #1-#2: dummies so ncu's capture slot (#4) lands on dcn_kernel
    warm_kernel<<<1, 32>>>(0);
    warm_kernel<<<1, 32>>>(1);

    dim3 g1(32, Nn);
    conv1_kernel<<<g1, 128>>>(x, mask, w1, b1);            // #3

    dim3 g2(Hh, Nn);
    dcn_kernel<<<g2, 128>>>(w_off, w_dcn, b_dcn, w2, b2);  // #4 <- profiled

    pool_kernel<<<dim3(16, Nn), 256>>>();

    // fc1: M=2048, K=8192, KS=8 -> 32x8 = 256 blocks
    fc_mma_bf16<8192, 4096, 1024, 2048, 0><<<dim3(32, 8), 256>>>(fc1_w);
    red1_kernel<<<512, 256>>>(fc1_b);

    // fc2: M=1024, K=2048, KS=8 -> 16x8 = 128 blocks
    fc_mma_bf16<2048, 1024, 256, 1024, 1><<<dim3(16, 8), 256>>>(fc2_w);
    red2_kernel<<<512, 256>>>(fc2_b);

    fc3_kernel<<<128, 256>>>(io_w, io_b, out);
}